// round 2
// baseline (speedup 1.0000x reference)
#include <cuda_runtime.h>
#include <cstdint>
#include <cstddef>

#define BATCH 32
#define CTOT 512
#define BR 256
#define LLEN 4096
#define TN 62            // output columns per tile
#define NCOL 64          // TN + 2 halo columns
#define SSTRIDE 65       // smem row stride (≡1 mod 32: conflict-minimal)
#define NTILES 8         // 8 n-tiles of 8 = 64 columns
#define NTHREADS 256
#define LTILES 67        // ceil(4096/62)
#define BN_EPS 1e-5f

// ---------------- device scratch (allocation-free) ----------------
__device__ unsigned char g_mask[BATCH * LLEN];
__device__ int g_mask_mode;

// ---------------- mask dtype detection + expansion ----------------
// int32 layout: bytes at i%4!=0 are all zero.
// float32 layout (0.0f/1.0f): bytes at i%4==0 are all zero.
// uint8/bool layout: both groups contain nonzero bytes.
__global__ void detect_mask_kernel(const unsigned char* __restrict__ m) {
    __shared__ unsigned sA[NTHREADS], sB[NTHREADS];
    unsigned a = 0, b = 0;
    for (int i = threadIdx.x; i < BATCH * LLEN; i += NTHREADS) {
        unsigned v = m[i];
        if ((i & 3) == 0) a |= v; else b |= v;
    }
    sA[threadIdx.x] = a; sB[threadIdx.x] = b;
    __syncthreads();
    for (int s = NTHREADS / 2; s > 0; s >>= 1) {
        if (threadIdx.x < s) { sA[threadIdx.x] |= sA[threadIdx.x + s]; sB[threadIdx.x] |= sB[threadIdx.x + s]; }
        __syncthreads();
    }
    if (threadIdx.x == 0)
        g_mask_mode = (sA[0] == 0) ? 2 : ((sB[0] == 0) ? 0 : 1);
}

__global__ void expand_mask_kernel(const void* __restrict__ m) {
    int i = blockIdx.x * blockDim.x + threadIdx.x;
    if (i >= BATCH * LLEN) return;
    int mode = g_mask_mode;
    unsigned char v;
    if (mode == 0)      v = (((const int*)m)[i] != 0);
    else if (mode == 1) v = (((const unsigned char*)m)[i] != 0);
    else                v = (((const float*)m)[i] != 0.f);
    g_mask[i] = v;
}

// ---------------- helpers ----------------
__device__ __forceinline__ unsigned f2tf32(float f) {
    unsigned r; asm("cvt.rna.tf32.f32 %0, %1;" : "=r"(r) : "f"(f)); return r;
}

// mish(x) = x * tanh(softplus(x)) = x * (z^2-1)/(z^2+1), z = 1+exp(x)
__device__ __forceinline__ float mishf(float x) {
    if (x > 30.f) return x;
    float z = 1.f + __expf(x);
    float z2 = z * z;
    return x * __fdividef(z2 - 1.f, z2 + 1.f);
}

__device__ __forceinline__ void mma8(float* c, const unsigned* a, unsigned b0, unsigned b1) {
    asm volatile(
        "mma.sync.aligned.m16n8k8.row.col.f32.tf32.tf32.f32 "
        "{%0,%1,%2,%3}, {%4,%5,%6,%7}, {%8,%9}, {%0,%1,%2,%3};\n"
        : "+f"(c[0]), "+f"(c[1]), "+f"(c[2]), "+f"(c[3])
        : "r"(a[0]), "r"(a[1]), "r"(a[2]), "r"(a[3]), "r"(b0), "r"(b1));
}

// ---------------- fused main kernel ----------------
__global__ void __launch_bounds__(NTHREADS, 1) fused_kernel(
    const float* __restrict__ x,  const float* __restrict__ w1,
    const float* __restrict__ w2, const float* __restrict__ w3,
    const float* __restrict__ b1w, const float* __restrict__ b1b,
    const float* __restrict__ b1m, const float* __restrict__ b1v,
    const float* __restrict__ b2w, const float* __restrict__ b2b,
    const float* __restrict__ b2m, const float* __restrict__ b2v,
    const float* __restrict__ b3w, const float* __restrict__ b3b,
    const float* __restrict__ b3m, const float* __restrict__ b3v,
    float* __restrict__ out)
{
    extern __shared__ float smem[];
    float* sX = smem;                       // [BR][SSTRIDE] : X2 tile -> bn1 output
    float* sY = smem + BR * SSTRIDE;        // [BR][SSTRIDE] : bn2 output (tf32 bits)
    unsigned* sXu = (unsigned*)sX;
    unsigned* sYu = (unsigned*)sY;
    __shared__ float sS1[BR], sT1[BR], sS2[BR], sT2[BR], sS3[BR], sT3[BR];
    __shared__ float sWa[BR], sWb[BR], sWc[BR];
    __shared__ unsigned char sMk[NCOL + 4];

    const int tid = threadIdx.x;
    const int bb = blockIdx.y;
    const int l0 = blockIdx.x * TN;

    // per-channel fused BN constants + conv weights
    {
        int ch = tid;
        float i1 = rsqrtf(b1v[ch] + BN_EPS); float s1 = b1w[ch] * i1;
        sS1[ch] = s1; sT1[ch] = b1b[ch] - s1 * b1m[ch];
        float i2 = rsqrtf(b2v[ch] + BN_EPS); float s2 = b2w[ch] * i2;
        sS2[ch] = s2; sT2[ch] = b2b[ch] - s2 * b2m[ch];
        float i3 = rsqrtf(b3v[ch] + BN_EPS); float s3 = b3w[ch] * i3;
        sS3[ch] = s3; sT3[ch] = b3b[ch] - s3 * b3m[ch];
        sWa[ch] = w2[ch * 3 + 0]; sWb[ch] = w2[ch * 3 + 1]; sWc[ch] = w2[ch * 3 + 2];
    }
    if (tid < NCOL + 4) {
        int l = l0 - 1 + tid;
        sMk[tid] = (tid < NCOL && l >= 0 && l < LLEN) ? g_mask[bb * LLEN + l] : 0;
    }

    // load X2 tile (cols: l0-1 .. l0+62), converted to tf32
    {
        const float* xb = x + ((size_t)bb * CTOT + BR) * LLEN;
        #pragma unroll 4
        for (int idx = tid; idx < BR * NCOL; idx += NTHREADS) {
            int k = idx >> 6, n = idx & 63;
            int l = l0 - 1 + n;
            float v = (l >= 0 && l < LLEN) ? xb[(size_t)k * LLEN + l] : 0.f;
            sXu[k * SSTRIDE + n] = f2tf32(v);
        }
    }
    // copy x1 into odd output channels (independent work, overlaps smem fill)
    {
        const float* x1b = x + (size_t)bb * CTOT * LLEN;
        float* ob = out + (size_t)bb * CTOT * LLEN;
        #pragma unroll 4
        for (int idx = tid; idx < BR * TN; idx += NTHREADS) {
            int i = idx / TN, n = idx - i * TN;
            int l = l0 + n;
            if (l < LLEN) ob[(size_t)(2 * i + 1) * LLEN + l] = x1b[(size_t)i * LLEN + l];
        }
    }
    __syncthreads();

    const int warp = tid >> 5, lane = tid & 31;
    const int g = lane >> 2, tg = lane & 3;
    const int m0 = warp * 32;
    const int rows[4] = { m0 + g, m0 + g + 8, m0 + 16 + g, m0 + 24 + g };

    float acc[2][NTILES][4];

    // ---------------- GEMM1: Y1 = W1 @ X2 (tf32 tensor cores) ----------------
    #pragma unroll
    for (int mt = 0; mt < 2; mt++)
        #pragma unroll
        for (int nt = 0; nt < NTILES; nt++)
            #pragma unroll
            for (int q = 0; q < 4; q++) acc[mt][nt][q] = 0.f;
    {
        const int r0 = rows[0] * BR, r1 = rows[1] * BR, r2 = rows[2] * BR, r3 = rows[3] * BR;
        #pragma unroll 2
        for (int k0 = 0; k0 < BR; k0 += 8) {
            unsigned a0[4], a1[4];
            a0[0] = f2tf32(w1[r0 + k0 + tg]);     a0[1] = f2tf32(w1[r1 + k0 + tg]);
            a0[2] = f2tf32(w1[r0 + k0 + tg + 4]); a0[3] = f2tf32(w1[r1 + k0 + tg + 4]);
            a1[0] = f2tf32(w1[r2 + k0 + tg]);     a1[1] = f2tf32(w1[r3 + k0 + tg]);
            a1[2] = f2tf32(w1[r2 + k0 + tg + 4]); a1[3] = f2tf32(w1[r3 + k0 + tg + 4]);
            #pragma unroll
            for (int nt = 0; nt < NTILES; nt++) {
                unsigned bb0 = sXu[(k0 + tg) * SSTRIDE + nt * 8 + g];
                unsigned bb1 = sXu[(k0 + tg + 4) * SSTRIDE + nt * 8 + g];
                mma8(acc[0][nt], a0, bb0, bb1);
                mma8(acc[1][nt], a1, bb0, bb1);
            }
        }
    }
    // epilogue 1: mish + bn1 + mask -> sX (fp32, reused buffer)
    {
        float sv[4], tv[4];
        #pragma unroll
        for (int q = 0; q < 4; q++) { sv[q] = sS1[rows[q]]; tv[q] = sT1[rows[q]]; }
        __syncthreads();   // all warps finished reading sX
        #pragma unroll
        for (int mt = 0; mt < 2; mt++)
            #pragma unroll
            for (int nt = 0; nt < NTILES; nt++)
                #pragma unroll
                for (int q = 0; q < 4; q++) {
                    int ri = mt * 2 + (q >> 1);
                    int col = nt * 8 + 2 * tg + (q & 1);
                    float y = mishf(acc[mt][nt][q]);
                    float z = sv[ri] * y + tv[ri];
                    sX[rows[ri] * SSTRIDE + col] = sMk[col] ? z : 0.f;
                }
    }
    __syncthreads();

    // ---------------- depthwise conv3 + bn2 + mask -> sY (tf32) ----------------
    {
        int ch = tid;
        float wa = sWa[ch], wb = sWb[ch], wc = sWc[ch];
        float s2 = sS2[ch], t2 = sT2[ch];
        const float* row = sX + ch * SSTRIDE;
        unsigned* orow = sYu + ch * SSTRIDE;
        float p0 = row[0], p1 = row[1];
        #pragma unroll 2
        for (int j = 0; j < TN; j++) {
            float p2 = row[j + 2];
            float c = wa * p0 + wb * p1 + wc * p2;
            float v = sMk[j + 1] ? (s2 * c + t2) : 0.f;
            orow[j] = f2tf32(v);
            p0 = p1; p1 = p2;
        }
        orow[TN] = 0u; orow[TN + 1] = 0u;  // zero pad cols 62,63 for GEMM3
    }
    __syncthreads();

    // ---------------- GEMM3: O = W3 @ Y2 ----------------
    #pragma unroll
    for (int mt = 0; mt < 2; mt++)
        #pragma unroll
        for (int nt = 0; nt < NTILES; nt++)
            #pragma unroll
            for (int q = 0; q < 4; q++) acc[mt][nt][q] = 0.f;
    {
        const int r0 = rows[0] * BR, r1 = rows[1] * BR, r2 = rows[2] * BR, r3 = rows[3] * BR;
        #pragma unroll 2
        for (int k0 = 0; k0 < BR; k0 += 8) {
            unsigned a0[4], a1[4];
            a0[0] = f2tf32(w3[r0 + k0 + tg]);     a0[1] = f2tf32(w3[r1 + k0 + tg]);
            a0[2] = f2tf32(w3[r0 + k0 + tg + 4]); a0[3] = f2tf32(w3[r1 + k0 + tg + 4]);
            a1[0] = f2tf32(w3[r2 + k0 + tg]);     a1[1] = f2tf32(w3[r3 + k0 + tg]);
            a1[2] = f2tf32(w3[r2 + k0 + tg + 4]); a1[3] = f2tf32(w3[r3 + k0 + tg + 4]);
            #pragma unroll
            for (int nt = 0; nt < NTILES; nt++) {
                unsigned bb0 = sYu[(k0 + tg) * SSTRIDE + nt * 8 + g];
                unsigned bb1 = sYu[(k0 + tg + 4) * SSTRIDE + nt * 8 + g];
                mma8(acc[0][nt], a0, bb0, bb1);
                mma8(acc[1][nt], a1, bb0, bb1);
            }
        }
    }
    // epilogue 3: mish + bn3 + mask -> even output channels (interleaved)
    {
        float sv[4], tv[4];
        #pragma unroll
        for (int q = 0; q < 4; q++) { sv[q] = sS3[rows[q]]; tv[q] = sT3[rows[q]]; }
        float* ob = out + (size_t)bb * CTOT * LLEN;
        #pragma unroll
        for (int mt = 0; mt < 2; mt++)
            #pragma unroll
            for (int nt = 0; nt < NTILES; nt++)
                #pragma unroll
                for (int q = 0; q < 4; q++) {
                    int ri = mt * 2 + (q >> 1);
                    int col = nt * 8 + 2 * tg + (q & 1);
                    int l = l0 + col;
                    if (col < TN && l < LLEN) {
                        float y = mishf(acc[mt][nt][q]);
                        float z = sv[ri] * y + tv[ri];
                        ob[(size_t)(2 * rows[ri]) * LLEN + l] = sMk[col + 1] ? z : 0.f;
                    }
                }
    }
}

// ---------------- launch ----------------
extern "C" void kernel_launch(void* const* d_in, const int* in_sizes, int n_in,
                              void* d_out, int out_size) {
    (void)in_sizes; (void)n_in; (void)out_size;
    const float* x   = (const float*)d_in[0];
    const void*  mk  = d_in[1];
    const float* w1  = (const float*)d_in[2];
    const float* w2  = (const float*)d_in[3];
    const float* w3  = (const float*)d_in[4];
    const float* b1w = (const float*)d_in[5];
    const float* b1b = (const float*)d_in[6];
    const float* b1m = (const float*)d_in[7];
    const float* b1v = (const float*)d_in[8];
    const float* b2w = (const float*)d_in[9];
    const float* b2b = (const float*)d_in[10];
    const float* b2m = (const float*)d_in[11];
    const float* b2v = (const float*)d_in[12];
    const float* b3w = (const float*)d_in[13];
    const float* b3b = (const float*)d_in[14];
    const float* b3m = (const float*)d_in[15];
    const float* b3v = (const float*)d_in[16];
    float* out = (float*)d_out;

    const int smem_bytes = 2 * BR * SSTRIDE * (int)sizeof(float);
    cudaFuncSetAttribute(fused_kernel, cudaFuncAttributeMaxDynamicSharedMemorySize, smem_bytes);

    detect_mask_kernel<<<1, NTHREADS>>>((const unsigned char*)mk);
    expand_mask_kernel<<<(BATCH * LLEN + 255) / 256, 256>>>(mk);

    dim3 grid(LTILES, BATCH);
    fused_kernel<<<grid, NTHREADS, smem_bytes>>>(
        x, w1, w2, w3,
        b1w, b1b, b1m, b1v,
        b2w, b2b, b2m, b2v,
        b3w, b3b, b3m, b3v,
        out);
}

// round 3
// speedup vs baseline: 2.0899x; 2.0899x over previous
#include <cuda_runtime.h>
#include <cstdint>
#include <cstddef>

#define BATCH 32
#define CTOT 512
#define BR 256
#define LLEN 4096
#define TN 62            // output columns per tile
#define NCOL 64          // TN + 2 halo columns
#define SSTRIDE 65       // smem row stride (conflict-minimal)
#define NTILES 8         // 8 n-tiles of 8 = 64 columns
#define NTHREADS 256
#define LTILES 67        // ceil(4096/62)
#define BN_EPS 1e-5f
#define DET_BLOCKS 128

// ---------------- device scratch (allocation-free) ----------------
__device__ unsigned char g_mask[BATCH * LLEN];
__device__ unsigned g_blkA[DET_BLOCKS], g_blkB[DET_BLOCKS];
__device__ unsigned g_w1t[BR * BR], g_w3t[BR * BR];

// ---------------- helpers ----------------
__device__ __forceinline__ unsigned f2tf32(float f) {
    unsigned r; asm("cvt.rna.tf32.f32 %0, %1;" : "=r"(r) : "f"(f)); return r;
}

// mish(x) = x * tanh(softplus(x)) = x * (z^2-1)/(z^2+1), z = 1+exp(x)
__device__ __forceinline__ float mishf(float x) {
    if (x > 30.f) return x;
    float z = 1.f + __expf(x);
    float z2 = z * z;
    return x * __fdividef(z2 - 1.f, z2 + 1.f);
}

__device__ __forceinline__ void mma8(float* c, const unsigned* a, unsigned b0, unsigned b1) {
    asm volatile(
        "mma.sync.aligned.m16n8k8.row.col.f32.tf32.tf32.f32 "
        "{%0,%1,%2,%3}, {%4,%5,%6,%7}, {%8,%9}, {%0,%1,%2,%3};\n"
        : "+f"(c[0]), "+f"(c[1]), "+f"(c[2]), "+f"(c[3])
        : "r"(a[0]), "r"(a[1]), "r"(a[2]), "r"(a[3]), "r"(b0), "r"(b1));
}

// ---------------- mask dtype detection (parallel, atomic-free) ----------------
// int32 layout: bytes at i%4!=0 are all zero.
// float32 layout (0.0f/1.0f): bytes at i%4==0 are all zero.
// uint8/bool layout: both groups contain nonzero bytes.
__global__ void detect_kernel(const unsigned char* __restrict__ m) {
    unsigned a = 0, b = 0;
    const int stride = DET_BLOCKS * 256;
    for (int i = blockIdx.x * 256 + threadIdx.x; i < BATCH * LLEN; i += stride) {
        unsigned v = m[i];
        if ((i & 3) == 0) a |= v; else b |= v;
    }
    a = __reduce_or_sync(0xffffffffu, a);
    b = __reduce_or_sync(0xffffffffu, b);
    __shared__ unsigned sa[8], sb[8];
    int w = threadIdx.x >> 5;
    if ((threadIdx.x & 31) == 0) { sa[w] = a; sb[w] = b; }
    __syncthreads();
    if (threadIdx.x == 0) {
        unsigned A = 0, B = 0;
        #pragma unroll
        for (int i = 0; i < 8; i++) { A |= sa[i]; B |= sb[i]; }
        g_blkA[blockIdx.x] = A; g_blkB[blockIdx.x] = B;
    }
}

// Expand mask to bytes + convert W1/W3 to tf32 (fused to keep launch count at 3)
__global__ void expand_conv_kernel(const void* __restrict__ m,
                                   const float* __restrict__ w1,
                                   const float* __restrict__ w3) {
    __shared__ int sMode;
    __shared__ unsigned swa[4], swb[4];
    if (threadIdx.x < DET_BLOCKS) {
        unsigned a = g_blkA[threadIdx.x], b = g_blkB[threadIdx.x];
        a = __reduce_or_sync(0xffffffffu, a);
        b = __reduce_or_sync(0xffffffffu, b);
        if ((threadIdx.x & 31) == 0) { swa[threadIdx.x >> 5] = a; swb[threadIdx.x >> 5] = b; }
    }
    __syncthreads();
    if (threadIdx.x == 0) {
        unsigned A = swa[0] | swa[1] | swa[2] | swa[3];
        unsigned B = swb[0] | swb[1] | swb[2] | swb[3];
        sMode = (A == 0) ? 2 : ((B == 0) ? 0 : 1);
    }
    __syncthreads();
    int i = blockIdx.x * 256 + threadIdx.x;
    if (i < BATCH * LLEN) {
        int mode = sMode;
        unsigned char v;
        if (mode == 0)      v = (((const int*)m)[i] != 0);
        else if (mode == 1) v = (((const unsigned char*)m)[i] != 0);
        else                v = (((const float*)m)[i] != 0.f);
        g_mask[i] = v;
    }
    if (i < BR * BR) {
        g_w1t[i] = f2tf32(w1[i]);
        g_w3t[i] = f2tf32(w3[i]);
    }
}

// ---------------- fused main kernel ----------------
__global__ void __launch_bounds__(NTHREADS, 2) fused_kernel(
    const float* __restrict__ x,
    const float* __restrict__ b1w, const float* __restrict__ b1b,
    const float* __restrict__ b1m, const float* __restrict__ b1v,
    const float* __restrict__ b2w, const float* __restrict__ b2b,
    const float* __restrict__ b2m, const float* __restrict__ b2v,
    const float* __restrict__ b3w, const float* __restrict__ b3b,
    const float* __restrict__ b3m, const float* __restrict__ b3v,
    const float* __restrict__ w2,
    float* __restrict__ out)
{
    extern __shared__ float smem[];
    float* sX = smem;                       // [BR][SSTRIDE] (single buffer, reused)
    unsigned* sXu = (unsigned*)sX;
    __shared__ float sS1[BR], sT1[BR], sS2[BR], sT2[BR], sS3[BR], sT3[BR];
    __shared__ float sWa[BR], sWb[BR], sWc[BR];
    __shared__ unsigned char sMk[NCOL + 4];

    const int tid = threadIdx.x;
    const int bb = blockIdx.y;
    const int l0 = blockIdx.x * TN;

    // per-channel fused BN constants + conv weights
    {
        int ch = tid;
        float i1 = rsqrtf(b1v[ch] + BN_EPS); float s1 = b1w[ch] * i1;
        sS1[ch] = s1; sT1[ch] = b1b[ch] - s1 * b1m[ch];
        float i2 = rsqrtf(b2v[ch] + BN_EPS); float s2 = b2w[ch] * i2;
        sS2[ch] = s2; sT2[ch] = b2b[ch] - s2 * b2m[ch];
        float i3 = rsqrtf(b3v[ch] + BN_EPS); float s3 = b3w[ch] * i3;
        sS3[ch] = s3; sT3[ch] = b3b[ch] - s3 * b3m[ch];
        sWa[ch] = w2[ch * 3 + 0]; sWb[ch] = w2[ch * 3 + 1]; sWc[ch] = w2[ch * 3 + 2];
    }
    if (tid < NCOL + 4) {
        int l = l0 - 1 + tid;
        sMk[tid] = (tid < NCOL && l >= 0 && l < LLEN) ? g_mask[bb * LLEN + l] : 0;
    }

    // load X2 tile (cols: l0-1 .. l0+62), converted to tf32
    {
        const float* xb = x + ((size_t)bb * CTOT + BR) * LLEN;
        #pragma unroll 4
        for (int idx = tid; idx < BR * NCOL; idx += NTHREADS) {
            int k = idx >> 6, n = idx & 63;
            int l = l0 - 1 + n;
            float v = (l >= 0 && l < LLEN) ? xb[(size_t)k * LLEN + l] : 0.f;
            sXu[k * SSTRIDE + n] = f2tf32(v);
        }
    }
    // copy x1 into odd output channels (coalesced, independent work)
    {
        const float* x1b = x + (size_t)bb * CTOT * LLEN;
        float* ob = out + (size_t)bb * CTOT * LLEN;
        #pragma unroll 4
        for (int idx = tid; idx < BR * NCOL; idx += NTHREADS) {
            int r = idx >> 6, c = idx & 63;
            int l = l0 + c;
            if (c < TN && l < LLEN)
                ob[(size_t)(2 * r + 1) * LLEN + l] = x1b[(size_t)r * LLEN + l];
        }
    }
    __syncthreads();

    const int warp = tid >> 5, lane = tid & 31;
    const int g = lane >> 2, tg = lane & 3;
    const int m0 = warp * 32;
    const int rows[4] = { m0 + g, m0 + g + 8, m0 + 16 + g, m0 + 24 + g };

    float acc[2][NTILES][4];

    // ---------------- GEMM1: Y1 = W1 @ X2 (tf32 tensor cores) ----------------
    #pragma unroll
    for (int mt = 0; mt < 2; mt++)
        #pragma unroll
        for (int nt = 0; nt < NTILES; nt++)
            #pragma unroll
            for (int q = 0; q < 4; q++) acc[mt][nt][q] = 0.f;
    {
        const int r0 = rows[0] * BR, r1 = rows[1] * BR, r2 = rows[2] * BR, r3 = rows[3] * BR;
        #pragma unroll 2
        for (int k0 = 0; k0 < BR; k0 += 8) {
            unsigned a0[4], a1[4];
            a0[0] = g_w1t[r0 + k0 + tg];     a0[1] = g_w1t[r1 + k0 + tg];
            a0[2] = g_w1t[r0 + k0 + tg + 4]; a0[3] = g_w1t[r1 + k0 + tg + 4];
            a1[0] = g_w1t[r2 + k0 + tg];     a1[1] = g_w1t[r3 + k0 + tg];
            a1[2] = g_w1t[r2 + k0 + tg + 4]; a1[3] = g_w1t[r3 + k0 + tg + 4];
            #pragma unroll
            for (int nt = 0; nt < NTILES; nt++) {
                unsigned bb0 = sXu[(k0 + tg) * SSTRIDE + nt * 8 + g];
                unsigned bb1 = sXu[(k0 + tg + 4) * SSTRIDE + nt * 8 + g];
                mma8(acc[0][nt], a0, bb0, bb1);
                mma8(acc[1][nt], a1, bb0, bb1);
            }
        }
    }
    // epilogue 1: mish + bn1 + mask -> sX (fp32, in place)
    {
        float sv[4], tv[4];
        #pragma unroll
        for (int q = 0; q < 4; q++) { sv[q] = sS1[rows[q]]; tv[q] = sT1[rows[q]]; }
        __syncthreads();   // all warps finished reading sX
        #pragma unroll
        for (int mt = 0; mt < 2; mt++)
            #pragma unroll
            for (int nt = 0; nt < NTILES; nt++)
                #pragma unroll
                for (int q = 0; q < 4; q++) {
                    int ri = mt * 2 + (q >> 1);
                    int col = nt * 8 + 2 * tg + (q & 1);
                    float y = mishf(acc[mt][nt][q]);
                    float z = sv[ri] * y + tv[ri];
                    sX[rows[ri] * SSTRIDE + col] = sMk[col] ? z : 0.f;
                }
    }
    __syncthreads();

    // ------- depthwise conv3 + bn2 + mask, IN PLACE (thread owns its row) -------
    {
        int ch = tid;
        float wa = sWa[ch], wb = sWb[ch], wc = sWc[ch];
        float s2 = sS2[ch], t2 = sT2[ch];
        float* row = sX + ch * SSTRIDE;
        unsigned* orow = sXu + ch * SSTRIDE;
        float p0 = row[0], p1 = row[1];
        #pragma unroll 2
        for (int j = 0; j < TN; j++) {
            float p2 = row[j + 2];
            float c = wa * p0 + wb * p1 + wc * p2;
            float v = sMk[j + 1] ? (s2 * c + t2) : 0.f;
            orow[j] = f2tf32(v);       // safe: in-place, sliding window in regs
            p0 = p1; p1 = p2;
        }
        orow[TN] = 0u; orow[TN + 1] = 0u;  // zero pad cols 62,63 for GEMM3
    }
    __syncthreads();

    // ---------------- GEMM3: O = W3 @ Y2 ----------------
    #pragma unroll
    for (int mt = 0; mt < 2; mt++)
        #pragma unroll
        for (int nt = 0; nt < NTILES; nt++)
            #pragma unroll
            for (int q = 0; q < 4; q++) acc[mt][nt][q] = 0.f;
    {
        const int r0 = rows[0] * BR, r1 = rows[1] * BR, r2 = rows[2] * BR, r3 = rows[3] * BR;
        #pragma unroll 2
        for (int k0 = 0; k0 < BR; k0 += 8) {
            unsigned a0[4], a1[4];
            a0[0] = g_w3t[r0 + k0 + tg];     a0[1] = g_w3t[r1 + k0 + tg];
            a0[2] = g_w3t[r0 + k0 + tg + 4]; a0[3] = g_w3t[r1 + k0 + tg + 4];
            a1[0] = g_w3t[r2 + k0 + tg];     a1[1] = g_w3t[r3 + k0 + tg];
            a1[2] = g_w3t[r2 + k0 + tg + 4]; a1[3] = g_w3t[r3 + k0 + tg + 4];
            #pragma unroll
            for (int nt = 0; nt < NTILES; nt++) {
                unsigned bb0 = sXu[(k0 + tg) * SSTRIDE + nt * 8 + g];
                unsigned bb1 = sXu[(k0 + tg + 4) * SSTRIDE + nt * 8 + g];
                mma8(acc[0][nt], a0, bb0, bb1);
                mma8(acc[1][nt], a1, bb0, bb1);
            }
        }
    }
    // epilogue 3: mish + bn3 + mask -> sX (staging for coalesced store)
    {
        float sv[4], tv[4];
        #pragma unroll
        for (int q = 0; q < 4; q++) { sv[q] = sS3[rows[q]]; tv[q] = sT3[rows[q]]; }
        __syncthreads();   // all warps finished reading sXu
        #pragma unroll
        for (int mt = 0; mt < 2; mt++)
            #pragma unroll
            for (int nt = 0; nt < NTILES; nt++)
                #pragma unroll
                for (int q = 0; q < 4; q++) {
                    int ri = mt * 2 + (q >> 1);
                    int col = nt * 8 + 2 * tg + (q & 1);
                    float y = mishf(acc[mt][nt][q]);
                    float z = sv[ri] * y + tv[ri];
                    sX[rows[ri] * SSTRIDE + col] = sMk[col + 1] ? z : 0.f;
                }
    }
    __syncthreads();

    // coalesced store: even output channels
    {
        float* ob = out + (size_t)bb * CTOT * LLEN;
        #pragma unroll 4
        for (int idx = tid; idx < BR * NCOL; idx += NTHREADS) {
            int r = idx >> 6, c = idx & 63;
            int l = l0 + c;
            if (c < TN && l < LLEN)
                ob[(size_t)(2 * r) * LLEN + l] = sX[r * SSTRIDE + c];
        }
    }
}

// ---------------- launch ----------------
extern "C" void kernel_launch(void* const* d_in, const int* in_sizes, int n_in,
                              void* d_out, int out_size) {
    (void)in_sizes; (void)n_in; (void)out_size;
    const float* x   = (const float*)d_in[0];
    const void*  mk  = d_in[1];
    const float* w1  = (const float*)d_in[2];
    const float* w2  = (const float*)d_in[3];
    const float* w3  = (const float*)d_in[4];
    const float* b1w = (const float*)d_in[5];
    const float* b1b = (const float*)d_in[6];
    const float* b1m = (const float*)d_in[7];
    const float* b1v = (const float*)d_in[8];
    const float* b2w = (const float*)d_in[9];
    const float* b2b = (const float*)d_in[10];
    const float* b2m = (const float*)d_in[11];
    const float* b2v = (const float*)d_in[12];
    const float* b3w = (const float*)d_in[13];
    const float* b3b = (const float*)d_in[14];
    const float* b3m = (const float*)d_in[15];
    const float* b3v = (const float*)d_in[16];
    float* out = (float*)d_out;

    const int smem_bytes = BR * SSTRIDE * (int)sizeof(float);
    cudaFuncSetAttribute(fused_kernel, cudaFuncAttributeMaxDynamicSharedMemorySize, smem_bytes);

    detect_kernel<<<DET_BLOCKS, 256>>>((const unsigned char*)mk);
    expand_conv_kernel<<<(BATCH * LLEN + 255) / 256, 256>>>(mk, w1, w3);

    dim3 grid(LTILES, BATCH);
    fused_kernel<<<grid, NTHREADS, smem_bytes>>>(
        x,
        b1w, b1b, b1m, b1v,
        b2w, b2b, b2m, b2v,
        b3w, b3b, b3m, b3v,
        w2, out);
}

// round 4
// speedup vs baseline: 2.9065x; 1.3907x over previous
#include <cuda_runtime.h>
#include <cstdint>
#include <cstddef>

#define BATCH 32
#define CTOT 512
#define BR 256
#define LLEN 4096
#define TN 62            // output columns per tile
#define NCOL 64          // TN + 2 halo columns
#define SST 264          // smem col stride in words (≡8 mod 32: conflict-free mainloop)
#define NTILES 8
#define NTHREADS 256
#define LTILES 67        // ceil(4096/62)
#define BN_EPS 1e-5f
#define DET_BLOCKS 128

// ---------------- device scratch (allocation-free) ----------------
__device__ unsigned g_blkA[DET_BLOCKS], g_blkB[DET_BLOCKS];
__device__ unsigned g_w1t[BR * BR], g_w3t[BR * BR];   // tf32, k-permuted

// k-permutation: maps k so that (k0+tg, k0+tg+4) land on adjacent words
__host__ __device__ __forceinline__ int kperm(int k) {
    return (k & ~7) | ((k & 3) << 1) | ((k >> 2) & 1);
}

__device__ __forceinline__ unsigned f2tf32(float f) {
    unsigned r; asm("cvt.rna.tf32.f32 %0, %1;" : "=r"(r) : "f"(f)); return r;
}

// mish(x) = x * tanh(softplus(x)) = x * (z^2-1)/(z^2+1), z = 1+exp(x)
__device__ __forceinline__ float mishf(float x) {
    if (x > 30.f) return x;
    float z = 1.f + __expf(x);
    float z2 = z * z;
    return x * __fdividef(z2 - 1.f, z2 + 1.f);
}

__device__ __forceinline__ void mma8(float* c, const unsigned* a, unsigned b0, unsigned b1) {
    asm volatile(
        "mma.sync.aligned.m16n8k8.row.col.f32.tf32.tf32.f32 "
        "{%0,%1,%2,%3}, {%4,%5,%6,%7}, {%8,%9}, {%0,%1,%2,%3};\n"
        : "+f"(c[0]), "+f"(c[1]), "+f"(c[2]), "+f"(c[3])
        : "r"(a[0]), "r"(a[1]), "r"(a[2]), "r"(a[3]), "r"(b0), "r"(b1));
}

// ------- mask dtype detection + W1/W3 tf32 convert+permute (one kernel) -------
// int32 layout: bytes at i%4!=0 are all zero.
// float32 layout (0.0f/1.0f): bytes at i%4==0 are all zero.
// uint8/bool layout: both groups contain nonzero bytes.
__global__ void detect_kernel(const unsigned char* __restrict__ m,
                              const float* __restrict__ w1,
                              const float* __restrict__ w3) {
    unsigned a = 0, b = 0;
    const int stride = DET_BLOCKS * 256;
    for (int i = blockIdx.x * 256 + threadIdx.x; i < BATCH * LLEN; i += stride) {
        unsigned v = m[i];
        if ((i & 3) == 0) a |= v; else b |= v;
    }
    a = __reduce_or_sync(0xffffffffu, a);
    b = __reduce_or_sync(0xffffffffu, b);
    __shared__ unsigned sa[8], sb[8];
    int w = threadIdx.x >> 5;
    if ((threadIdx.x & 31) == 0) { sa[w] = a; sb[w] = b; }
    __syncthreads();
    if (threadIdx.x == 0) {
        unsigned A = 0, B = 0;
        #pragma unroll
        for (int i = 0; i < 8; i++) { A |= sa[i]; B |= sb[i]; }
        g_blkA[blockIdx.x] = A; g_blkB[blockIdx.x] = B;
    }
    // convert + k-permute weights (coalesced read, permuted-within-8 write)
    for (int i = blockIdx.x * 256 + threadIdx.x; i < BR * BR; i += stride) {
        int row = i >> 8, k = i & 255;
        int kp = kperm(k);
        g_w1t[(row << 8) + kp] = f2tf32(w1[i]);
        g_w3t[(row << 8) + kp] = f2tf32(w3[i]);
    }
}

// ---------------- fused main kernel ----------------
__global__ void __launch_bounds__(NTHREADS, 2) fused_kernel(
    const float* __restrict__ x, const void* __restrict__ mk,
    const float* __restrict__ b1w, const float* __restrict__ b1b,
    const float* __restrict__ b1m, const float* __restrict__ b1v,
    const float* __restrict__ b2w, const float* __restrict__ b2b,
    const float* __restrict__ b2m, const float* __restrict__ b2v,
    const float* __restrict__ b3w, const float* __restrict__ b3b,
    const float* __restrict__ b3m, const float* __restrict__ b3v,
    const float* __restrict__ w2,
    float* __restrict__ out)
{
    extern __shared__ float smem[];            // [NCOL][SST] transposed tile
    float* sX = smem;
    unsigned* sXu = (unsigned*)sX;
    __shared__ float sS1[BR], sT1[BR], sS2[BR], sT2[BR], sS3[BR], sT3[BR];
    __shared__ float sWa[BR], sWb[BR], sWc[BR];
    __shared__ unsigned char sMk[NCOL + 4];
    __shared__ int sMode;

    const int tid = threadIdx.x;
    const int bb = blockIdx.y;
    const int l0 = blockIdx.x * TN;

    // mask dtype mode (reduce detect blocks' partials)
    if (tid < 32) {
        unsigned A = 0, B = 0;
        for (int i = tid; i < DET_BLOCKS; i += 32) { A |= g_blkA[i]; B |= g_blkB[i]; }
        A = __reduce_or_sync(0xffffffffu, A);
        B = __reduce_or_sync(0xffffffffu, B);
        if (tid == 0) sMode = (A == 0) ? 2 : ((B == 0) ? 0 : 1);
    }
    // per-channel fused BN constants + conv weights
    {
        int ch = tid;
        float i1 = rsqrtf(b1v[ch] + BN_EPS); float s1 = b1w[ch] * i1;
        sS1[ch] = s1; sT1[ch] = b1b[ch] - s1 * b1m[ch];
        float i2 = rsqrtf(b2v[ch] + BN_EPS); float s2 = b2w[ch] * i2;
        sS2[ch] = s2; sT2[ch] = b2b[ch] - s2 * b2m[ch];
        float i3 = rsqrtf(b3v[ch] + BN_EPS); float s3 = b3w[ch] * i3;
        sS3[ch] = s3; sT3[ch] = b3b[ch] - s3 * b3m[ch];
        sWa[ch] = w2[ch * 3 + 0]; sWb[ch] = w2[ch * 3 + 1]; sWc[ch] = w2[ch * 3 + 2];
    }

    // load X2 tile (cols l0-1 .. l0+62) transposed + k-permuted, as tf32
    {
        const float* xb = x + ((size_t)bb * CTOT + BR) * LLEN;
        #pragma unroll 4
        for (int idx = tid; idx < BR * NCOL; idx += NTHREADS) {
            int k = idx >> 6, n = idx & 63;
            int kp = kperm(k);
            int l = l0 - 1 + n;
            float v = (l >= 0 && l < LLEN) ? xb[(size_t)k * LLEN + l] : 0.f;
            sXu[n * SST + kp] = f2tf32(v);
        }
    }
    // copy x1 into odd output channels (independent work)
    {
        const float* x1b = x + (size_t)bb * CTOT * LLEN;
        float* ob = out + (size_t)bb * CTOT * LLEN;
        #pragma unroll 4
        for (int idx = tid; idx < BR * NCOL; idx += NTHREADS) {
            int r = idx >> 6, c = idx & 63;
            int l = l0 + c;
            if (c < TN && l < LLEN)
                ob[(size_t)(2 * r + 1) * LLEN + l] = x1b[(size_t)r * LLEN + l];
        }
    }
    __syncthreads();

    // fill per-tile mask bytes (needs sMode; consumed after next sync)
    if (tid < NCOL + 4) {
        int l = l0 - 1 + tid;
        unsigned char v = 0;
        if (tid < NCOL && l >= 0 && l < LLEN) {
            int mode = sMode;
            size_t i = (size_t)bb * LLEN + l;
            if (mode == 0)      v = (((const int*)mk)[i] != 0);
            else if (mode == 1) v = (((const unsigned char*)mk)[i] != 0);
            else                v = (((const float*)mk)[i] != 0.f);
        }
        sMk[tid] = v;
    }

    const int warp = tid >> 5, lane = tid & 31;
    const int g = lane >> 2, tg = lane & 3;
    const int m0 = warp * 32;
    const int rows4[4] = { m0 + g, m0 + g + 8, m0 + 16 + g, m0 + 24 + g };
    int kprow[4];
    #pragma unroll
    for (int q = 0; q < 4; q++) kprow[q] = kperm(rows4[q]);

    float acc[2][NTILES][4];

    // ---------------- GEMM1: Y1 = W1 @ X2 ----------------
    #pragma unroll
    for (int mt = 0; mt < 2; mt++)
        #pragma unroll
        for (int nt = 0; nt < NTILES; nt++)
            #pragma unroll
            for (int q = 0; q < 4; q++) acc[mt][nt][q] = 0.f;
    {
        const unsigned* wbase = g_w1t;
        const int ro0 = rows4[0] << 8, ro1 = rows4[1] << 8, ro2 = rows4[2] << 8, ro3 = rows4[3] << 8;
        #pragma unroll 2
        for (int k0 = 0; k0 < BR; k0 += 8) {
            const int kk = k0 + 2 * tg;
            uint2 A0 = *(const uint2*)&wbase[ro0 + kk];
            uint2 A1 = *(const uint2*)&wbase[ro1 + kk];
            uint2 A2 = *(const uint2*)&wbase[ro2 + kk];
            uint2 A3 = *(const uint2*)&wbase[ro3 + kk];
            unsigned a0[4] = { A0.x, A1.x, A0.y, A1.y };
            unsigned a1[4] = { A2.x, A3.x, A2.y, A3.y };
            #pragma unroll
            for (int nt = 0; nt < NTILES; nt++) {
                uint2 Bv = *(const uint2*)&sXu[(nt * 8 + g) * SST + kk];
                mma8(acc[0][nt], a0, Bv.x, Bv.y);
                mma8(acc[1][nt], a1, Bv.x, Bv.y);
            }
        }
    }
    // epilogue 1: mish + bn1 + mask -> sX (transposed, in place)
    {
        float sv[4], tv[4];
        #pragma unroll
        for (int q = 0; q < 4; q++) { sv[q] = sS1[rows4[q]]; tv[q] = sT1[rows4[q]]; }
        __syncthreads();   // all warps finished reading sX
        #pragma unroll
        for (int mt = 0; mt < 2; mt++)
            #pragma unroll
            for (int nt = 0; nt < NTILES; nt++)
                #pragma unroll
                for (int q = 0; q < 4; q++) {
                    int ri = mt * 2 + (q >> 1);
                    int col = nt * 8 + 2 * tg + (q & 1);
                    float y = mishf(acc[mt][nt][q]);
                    float z = sv[ri] * y + tv[ri];
                    sX[col * SST + kprow[ri]] = sMk[col] ? z : 0.f;
                }
    }
    __syncthreads();

    // ------- depthwise conv3 + bn2 + mask, in place (thread owns its channel) -------
    {
        int ch = tid;
        float wa = sWa[ch], wb = sWb[ch], wc = sWc[ch];
        float s2 = sS2[ch], t2 = sT2[ch];
        float* colp = sX + kperm(ch);
        unsigned* colu = (unsigned*)colp;
        float p0 = colp[0 * SST], p1 = colp[1 * SST];
        #pragma unroll 2
        for (int j = 0; j < TN; j++) {
            float p2 = colp[(j + 2) * SST];
            float c = wa * p0 + wb * p1 + wc * p2;
            float v = sMk[j + 1] ? (s2 * c + t2) : 0.f;
            colu[j * SST] = f2tf32(v);   // safe: sliding window in regs
            p0 = p1; p1 = p2;
        }
        colu[TN * SST] = 0u; colu[(TN + 1) * SST] = 0u;  // zero pad cols 62,63
    }
    __syncthreads();

    // ---------------- GEMM3: O = W3 @ Y2 ----------------
    #pragma unroll
    for (int mt = 0; mt < 2; mt++)
        #pragma unroll
        for (int nt = 0; nt < NTILES; nt++)
            #pragma unroll
            for (int q = 0; q < 4; q++) acc[mt][nt][q] = 0.f;
    {
        const unsigned* wbase = g_w3t;
        const int ro0 = rows4[0] << 8, ro1 = rows4[1] << 8, ro2 = rows4[2] << 8, ro3 = rows4[3] << 8;
        #pragma unroll 2
        for (int k0 = 0; k0 < BR; k0 += 8) {
            const int kk = k0 + 2 * tg;
            uint2 A0 = *(const uint2*)&wbase[ro0 + kk];
            uint2 A1 = *(const uint2*)&wbase[ro1 + kk];
            uint2 A2 = *(const uint2*)&wbase[ro2 + kk];
            uint2 A3 = *(const uint2*)&wbase[ro3 + kk];
            unsigned a0[4] = { A0.x, A1.x, A0.y, A1.y };
            unsigned a1[4] = { A2.x, A3.x, A2.y, A3.y };
            #pragma unroll
            for (int nt = 0; nt < NTILES; nt++) {
                uint2 Bv = *(const uint2*)&sXu[(nt * 8 + g) * SST + kk];
                mma8(acc[0][nt], a0, Bv.x, Bv.y);
                mma8(acc[1][nt], a1, Bv.x, Bv.y);
            }
        }
    }
    // epilogue 3: mish + bn3 + mask -> even output channels, direct global
    // (quad writes 8 consecutive floats = full 32B sectors: no write amplification)
    {
        float sv[4], tv[4];
        #pragma unroll
        for (int q = 0; q < 4; q++) { sv[q] = sS3[rows4[q]]; tv[q] = sT3[rows4[q]]; }
        float* ob = out + (size_t)bb * CTOT * LLEN;
        #pragma unroll
        for (int mt = 0; mt < 2; mt++)
            #pragma unroll
            for (int nt = 0; nt < NTILES; nt++)
                #pragma unroll
                for (int q = 0; q < 4; q++) {
                    int ri = mt * 2 + (q >> 1);
                    int col = nt * 8 + 2 * tg + (q & 1);
                    int l = l0 + col;
                    if (col < TN && l < LLEN) {
                        float y = mishf(acc[mt][nt][q]);
                        float z = sv[ri] * y + tv[ri];
                        ob[(size_t)(2 * rows4[ri]) * LLEN + l] = sMk[col + 1] ? z : 0.f;
                    }
                }
    }
}

// ---------------- launch ----------------
extern "C" void kernel_launch(void* const* d_in, const int* in_sizes, int n_in,
                              void* d_out, int out_size) {
    (void)in_sizes; (void)n_in; (void)out_size;
    const float* x   = (const float*)d_in[0];
    const void*  mk  = d_in[1];
    const float* w1  = (const float*)d_in[2];
    const float* w2  = (const float*)d_in[3];
    const float* w3  = (const float*)d_in[4];
    const float* b1w = (const float*)d_in[5];
    const float* b1b = (const float*)d_in[6];
    const float* b1m = (const float*)d_in[7];
    const float* b1v = (const float*)d_in[8];
    const float* b2w = (const float*)d_in[9];
    const float* b2b = (const float*)d_in[10];
    const float* b2m = (const float*)d_in[11];
    const float* b2v = (const float*)d_in[12];
    const float* b3w = (const float*)d_in[13];
    const float* b3b = (const float*)d_in[14];
    const float* b3m = (const float*)d_in[15];
    const float* b3v = (const float*)d_in[16];
    float* out = (float*)d_out;

    const int smem_bytes = NCOL * SST * (int)sizeof(float);
    cudaFuncSetAttribute(fused_kernel, cudaFuncAttributeMaxDynamicSharedMemorySize, smem_bytes);

    detect_kernel<<<DET_BLOCKS, 256>>>((const unsigned char*)mk, w1, w3);

    dim3 grid(LTILES, BATCH);
    fused_kernel<<<grid, NTHREADS, smem_bytes>>>(
        x, mk,
        b1w, b1b, b1m, b1v,
        b2w, b2b, b2m, b2v,
        b3w, b3b, b3m, b3v,
        w2, out);
}

// round 5
// speedup vs baseline: 4.2863x; 1.4747x over previous
#include <cuda_runtime.h>
#include <cuda_fp16.h>
#include <cstdint>
#include <cstddef>

#define BATCH 32
#define CTOT 512
#define BR 256
#define LLEN 4096
#define TN 62            // output columns per tile
#define NCOL 64          // TN + 2 halo columns
#define SBW 136          // fp16 B-tile col stride in 32-bit words (≡8 mod 32)
#define SY 260           // fp32 Y1 staging col stride in words (≡4 mod 32)
#define NTILES 8
#define NTHREADS 256
#define LTILES 67        // ceil(4096/62)
#define BN_EPS 1e-5f
#define DET_BLOCKS 128

// ---------------- device scratch (allocation-free) ----------------
__device__ unsigned g_blkA[DET_BLOCKS], g_blkB[DET_BLOCKS];
__device__ unsigned g_w1h[BR * 128], g_w3h[BR * 128];   // half2-packed, word-permuted

// word permutation within 8-word (k16) group: orig word tg -> pos 2tg, tg+4 -> 2tg+1
__host__ __device__ __forceinline__ int wperm(int w) {
    return (w & ~7) | ((w & 3) << 1) | ((w >> 2) & 1);
}

__device__ __forceinline__ unsigned packh2(float lo, float hi) {
    __half2 h = __floats2half2_rn(lo, hi);
    return *reinterpret_cast<unsigned*>(&h);
}

// mish(x) = x * tanh(softplus(x)) = x * (z^2-1)/(z^2+1), z = 1+exp(x)
__device__ __forceinline__ float mishf(float x) {
    if (x > 30.f) return x;
    float z = 1.f + __expf(x);
    float z2 = z * z;
    return x * __fdividef(z2 - 1.f, z2 + 1.f);
}

__device__ __forceinline__ void mma16(float* c, const unsigned* a, unsigned b0, unsigned b1) {
    asm volatile(
        "mma.sync.aligned.m16n8k16.row.col.f32.f16.f16.f32 "
        "{%0,%1,%2,%3}, {%4,%5,%6,%7}, {%8,%9}, {%0,%1,%2,%3};\n"
        : "+f"(c[0]), "+f"(c[1]), "+f"(c[2]), "+f"(c[3])
        : "r"(a[0]), "r"(a[1]), "r"(a[2]), "r"(a[3]), "r"(b0), "r"(b1));
}

// ------- mask dtype detection + W1/W3 fp16 convert+permute -------
// int32 layout: bytes at i%4!=0 are all zero.
// float32 layout (0.0f/1.0f): bytes at i%4==0 are all zero.
// uint8/bool layout: both groups contain nonzero bytes.
__global__ void detect_kernel(const unsigned char* __restrict__ m,
                              const float* __restrict__ w1,
                              const float* __restrict__ w3) {
    unsigned a = 0, b = 0;
    const int stride = DET_BLOCKS * 256;
    for (int i = blockIdx.x * 256 + threadIdx.x; i < BATCH * LLEN; i += stride) {
        unsigned v = m[i];
        if ((i & 3) == 0) a |= v; else b |= v;
    }
    a = __reduce_or_sync(0xffffffffu, a);
    b = __reduce_or_sync(0xffffffffu, b);
    __shared__ unsigned sa[8], sb[8];
    int w = threadIdx.x >> 5;
    if ((threadIdx.x & 31) == 0) { sa[w] = a; sb[w] = b; }
    __syncthreads();
    if (threadIdx.x == 0) {
        unsigned A = 0, B = 0;
        #pragma unroll
        for (int i = 0; i < 8; i++) { A |= sa[i]; B |= sb[i]; }
        g_blkA[blockIdx.x] = A; g_blkB[blockIdx.x] = B;
    }
    // convert + word-permute weights: word w holds k=2w,2w+1 as half2
    for (int i = blockIdx.x * 256 + threadIdx.x; i < BR * 128; i += stride) {
        int row = i >> 7, w2i = i & 127;
        int wp = wperm(w2i);
        g_w1h[(row << 7) + wp] = packh2(w1[row * 256 + 2 * w2i], w1[row * 256 + 2 * w2i + 1]);
        g_w3h[(row << 7) + wp] = packh2(w3[row * 256 + 2 * w2i], w3[row * 256 + 2 * w2i + 1]);
    }
}

// ---------------- fused main kernel ----------------
__global__ void __launch_bounds__(NTHREADS, 2) fused_kernel(
    const float* __restrict__ x, const void* __restrict__ mk,
    const float* __restrict__ b1w, const float* __restrict__ b1b,
    const float* __restrict__ b1m, const float* __restrict__ b1v,
    const float* __restrict__ b2w, const float* __restrict__ b2b,
    const float* __restrict__ b2m, const float* __restrict__ b2v,
    const float* __restrict__ b3w, const float* __restrict__ b3b,
    const float* __restrict__ b3m, const float* __restrict__ b3v,
    const float* __restrict__ w2,
    float* __restrict__ out)
{
    extern __shared__ unsigned smem[];
    unsigned* sB = smem;                        // [NCOL][SBW] fp16 B-tile (half2 words)
    float* sY1 = (float*)(smem + NCOL * SBW);   // [NCOL][SY] fp32 Y1 staging
    __shared__ float sS1[BR], sT1[BR], sS2[BR], sT2[BR], sS3[BR], sT3[BR];
    __shared__ float sWa[BR], sWb[BR], sWc[BR];
    __shared__ unsigned char sMk[NCOL + 4];
    __shared__ int sMode;

    const int tid = threadIdx.x;
    const int bb = blockIdx.y;
    const int l0 = blockIdx.x * TN;

    // mask dtype mode (reduce detect blocks' partials)
    if (tid < 32) {
        unsigned A = 0, B = 0;
        for (int i = tid; i < DET_BLOCKS; i += 32) { A |= g_blkA[i]; B |= g_blkB[i]; }
        A = __reduce_or_sync(0xffffffffu, A);
        B = __reduce_or_sync(0xffffffffu, B);
        if (tid == 0) sMode = (A == 0) ? 2 : ((B == 0) ? 0 : 1);
    }
    // per-channel fused BN constants + conv weights
    {
        int ch = tid;
        float i1 = rsqrtf(b1v[ch] + BN_EPS); float s1 = b1w[ch] * i1;
        sS1[ch] = s1; sT1[ch] = b1b[ch] - s1 * b1m[ch];
        float i2 = rsqrtf(b2v[ch] + BN_EPS); float s2 = b2w[ch] * i2;
        sS2[ch] = s2; sT2[ch] = b2b[ch] - s2 * b2m[ch];
        float i3 = rsqrtf(b3v[ch] + BN_EPS); float s3 = b3w[ch] * i3;
        sS3[ch] = s3; sT3[ch] = b3b[ch] - s3 * b3m[ch];
        sWa[ch] = w2[ch * 3 + 0]; sWb[ch] = w2[ch * 3 + 1]; sWc[ch] = w2[ch * 3 + 2];
    }

    // load X2 tile (cols l0-1 .. l0+62): pack k-pairs to fp16, word-permuted
    {
        const float* xb = x + ((size_t)bb * CTOT + BR) * LLEN;
        #pragma unroll 4
        for (int idx = tid; idx < 128 * NCOL; idx += NTHREADS) {
            int w = idx >> 6, n = idx & 63;
            int l = l0 - 1 + n;
            float v0 = 0.f, v1 = 0.f;
            if (l >= 0 && l < LLEN) {
                const float* p = xb + (size_t)(2 * w) * LLEN + l;
                v0 = p[0]; v1 = p[LLEN];
            }
            sB[n * SBW + wperm(w)] = packh2(v0, v1);
        }
    }
    // copy x1 into odd output channels (independent work)
    {
        const float* x1b = x + (size_t)bb * CTOT * LLEN;
        float* ob = out + (size_t)bb * CTOT * LLEN;
        #pragma unroll 4
        for (int idx = tid; idx < BR * NCOL; idx += NTHREADS) {
            int r = idx >> 6, c = idx & 63;
            int l = l0 + c;
            if (c < TN && l < LLEN)
                ob[(size_t)(2 * r + 1) * LLEN + l] = x1b[(size_t)r * LLEN + l];
        }
    }
    __syncthreads();

    // fill per-tile mask bytes (needs sMode; consumed after next sync)
    if (tid < NCOL + 4) {
        int l = l0 - 1 + tid;
        unsigned char v = 0;
        if (tid < NCOL && l >= 0 && l < LLEN) {
            int mode = sMode;
            size_t i = (size_t)bb * LLEN + l;
            if (mode == 0)      v = (((const int*)mk)[i] != 0);
            else if (mode == 1) v = (((const unsigned char*)mk)[i] != 0);
            else                v = (((const float*)mk)[i] != 0.f);
        }
        sMk[tid] = v;
    }

    const int warp = tid >> 5, lane = tid & 31;
    const int g = lane >> 2, tg = lane & 3;
    const int m0 = warp * 32;
    const int rows4[4] = { m0 + g, m0 + g + 8, m0 + 16 + g, m0 + 24 + g };

    float acc[2][NTILES][4];

    // ---------------- GEMM1: Y1 = W1 @ X2 (fp16 m16n8k16) ----------------
    #pragma unroll
    for (int mt = 0; mt < 2; mt++)
        #pragma unroll
        for (int nt = 0; nt < NTILES; nt++)
            #pragma unroll
            for (int q = 0; q < 4; q++) acc[mt][nt][q] = 0.f;
    {
        const unsigned* wb = g_w1h;
        const int ro0 = rows4[0] << 7, ro1 = rows4[1] << 7, ro2 = rows4[2] << 7, ro3 = rows4[3] << 7;
        #pragma unroll
        for (int it = 0; it < 16; it++) {
            const int kw = it * 8 + 2 * tg;
            uint2 A0 = *(const uint2*)&wb[ro0 + kw];
            uint2 A1 = *(const uint2*)&wb[ro1 + kw];
            uint2 A2 = *(const uint2*)&wb[ro2 + kw];
            uint2 A3 = *(const uint2*)&wb[ro3 + kw];
            unsigned a0[4] = { A0.x, A1.x, A0.y, A1.y };
            unsigned a1[4] = { A2.x, A3.x, A2.y, A3.y };
            #pragma unroll
            for (int nt = 0; nt < NTILES; nt++) {
                uint2 Bv = *(const uint2*)&sB[(nt * 8 + g) * SBW + kw];
                mma16(acc[0][nt], a0, Bv.x, Bv.y);
                mma16(acc[1][nt], a1, Bv.x, Bv.y);
            }
        }
    }
    // epilogue 1: mish + bn1 + mask -> sY1 (fp32, separate buffer: no hazard)
    {
        float sv[4], tv[4];
        #pragma unroll
        for (int q = 0; q < 4; q++) { sv[q] = sS1[rows4[q]]; tv[q] = sT1[rows4[q]]; }
        #pragma unroll
        for (int mt = 0; mt < 2; mt++)
            #pragma unroll
            for (int nt = 0; nt < NTILES; nt++)
                #pragma unroll
                for (int q = 0; q < 4; q++) {
                    int ri = mt * 2 + (q >> 1);
                    int col = nt * 8 + 2 * tg + (q & 1);
                    float y = mishf(acc[mt][nt][q]);
                    float z = sv[ri] * y + tv[ri];
                    sY1[col * SY + rows4[ri]] = sMk[col] ? z : 0.f;
                }
    }
    __syncthreads();

    // ------- depthwise conv3 + bn2 + mask: read sY1 fp32, write fp16 B-tile -------
    {
        int ch = tid;
        float wa = sWa[ch], wb_ = sWb[ch], wc = sWc[ch];
        float s2 = sS2[ch], t2 = sT2[ch];
        const float* colp = sY1 + ch;
        __half* sBh = (__half*)sB;
        const int hoff = wperm(ch >> 1) * 2 + (ch & 1);
        float p0 = colp[0 * SY], p1 = colp[1 * SY];
        #pragma unroll 2
        for (int j = 0; j < TN; j++) {
            float p2 = colp[(j + 2) * SY];
            float c = wa * p0 + wb_ * p1 + wc * p2;
            float v = sMk[j + 1] ? (s2 * c + t2) : 0.f;
            sBh[j * (2 * SBW) + hoff] = __float2half_rn(v);
            p0 = p1; p1 = p2;
        }
        // zero pad cols 62,63 (k-words 0..127)
        sB[62 * SBW + (tid >> 1)] = 0u;
        sB[63 * SBW + 64 + (tid >> 1)] = 0u;
        if (tid < 128) sB[63 * SBW + tid] = 0u;
        else sB[62 * SBW + (tid - 128)] = 0u;
    }
    __syncthreads();

    // ---------------- GEMM3: O = W3 @ Y2 ----------------
    #pragma unroll
    for (int mt = 0; mt < 2; mt++)
        #pragma unroll
        for (int nt = 0; nt < NTILES; nt++)
            #pragma unroll
            for (int q = 0; q < 4; q++) acc[mt][nt][q] = 0.f;
    {
        const unsigned* wb = g_w3h;
        const int ro0 = rows4[0] << 7, ro1 = rows4[1] << 7, ro2 = rows4[2] << 7, ro3 = rows4[3] << 7;
        #pragma unroll
        for (int it = 0; it < 16; it++) {
            const int kw = it * 8 + 2 * tg;
            uint2 A0 = *(const uint2*)&wb[ro0 + kw];
            uint2 A1 = *(const uint2*)&wb[ro1 + kw];
            uint2 A2 = *(const uint2*)&wb[ro2 + kw];
            uint2 A3 = *(const uint2*)&wb[ro3 + kw];
            unsigned a0[4] = { A0.x, A1.x, A0.y, A1.y };
            unsigned a1[4] = { A2.x, A3.x, A2.y, A3.y };
            #pragma unroll
            for (int nt = 0; nt < NTILES; nt++) {
                uint2 Bv = *(const uint2*)&sB[(nt * 8 + g) * SBW + kw];
                mma16(acc[0][nt], a0, Bv.x, Bv.y);
                mma16(acc[1][nt], a1, Bv.x, Bv.y);
            }
        }
    }
    // epilogue 3: mish + bn3 + mask -> even output channels, STG.64 pairs
    {
        float sv[4], tv[4];
        #pragma unroll
        for (int q = 0; q < 4; q++) { sv[q] = sS3[rows4[q]]; tv[q] = sT3[rows4[q]]; }
        float* ob = out + (size_t)bb * CTOT * LLEN;
        #pragma unroll
        for (int mt = 0; mt < 2; mt++)
            #pragma unroll
            for (int nt = 0; nt < NTILES; nt++)
                #pragma unroll
                for (int qp = 0; qp < 2; qp++) {         // q pairs (0,1) and (2,3)
                    int ri = mt * 2 + qp;
                    int c0 = nt * 8 + 2 * tg;
                    int l = l0 + c0;
                    if (c0 < TN - 1 && l + 1 < LLEN) {
                        float y0 = mishf(acc[mt][nt][2 * qp + 0]);
                        float y1 = mishf(acc[mt][nt][2 * qp + 1]);
                        float z0 = sv[ri] * y0 + tv[ri];
                        float z1 = sv[ri] * y1 + tv[ri];
                        float2 zz;
                        zz.x = sMk[c0 + 1] ? z0 : 0.f;
                        zz.y = sMk[c0 + 2] ? z1 : 0.f;
                        *(float2*)&ob[(size_t)(2 * rows4[ri]) * LLEN + l] = zz;
                    }
                }
    }
}

// ---------------- launch ----------------
extern "C" void kernel_launch(void* const* d_in, const int* in_sizes, int n_in,
                              void* d_out, int out_size) {
    (void)in_sizes; (void)n_in; (void)out_size;
    const float* x   = (const float*)d_in[0];
    const void*  mk  = d_in[1];
    const float* w1  = (const float*)d_in[2];
    const float* w2  = (const float*)d_in[3];
    const float* w3  = (const float*)d_in[4];
    const float* b1w = (const float*)d_in[5];
    const float* b1b = (const float*)d_in[6];
    const float* b1m = (const float*)d_in[7];
    const float* b1v = (const float*)d_in[8];
    const float* b2w = (const float*)d_in[9];
    const float* b2b = (const float*)d_in[10];
    const float* b2m = (const float*)d_in[11];
    const float* b2v = (const float*)d_in[12];
    const float* b3w = (const float*)d_in[13];
    const float* b3b = (const float*)d_in[14];
    const float* b3m = (const float*)d_in[15];
    const float* b3v = (const float*)d_in[16];
    float* out = (float*)d_out;

    const int smem_bytes = (NCOL * SBW + NCOL * SY) * (int)sizeof(unsigned);
    cudaFuncSetAttribute(fused_kernel, cudaFuncAttributeMaxDynamicSharedMemorySize, smem_bytes);

    detect_kernel<<<DET_BLOCKS, 256>>>((const unsigned char*)mk, w1, w3);

    dim3 grid(LTILES, BATCH);
    fused_kernel<<<grid, NTHREADS, smem_bytes>>>(
        x, mk,
        b1w, b1b, b1m, b1v,
        b2w, b2b, b2m, b2v,
        b3w, b3b, b3m, b3v,
        w2, out);
}

// round 7
// speedup vs baseline: 4.3586x; 1.0169x over previous
#include <cuda_runtime.h>
#include <cuda_fp16.h>
#include <cstdint>
#include <cstddef>

#define BATCH 32
#define CTOT 512
#define BR 256
#define LLEN 4096
#define TN 62            // output columns per tile
#define NCOL 64          // TN + 2 halo columns
#define SBW 136          // fp16 B-tile col stride in 32-bit words (≡8 mod 32)
#define NTHREADS 256
#define LTILES 67        // ceil(4096/62)
#define BN_EPS 1e-5f
#define DET_BLOCKS 128

// ---------------- device scratch (allocation-free) ----------------
__device__ unsigned g_blkA[DET_BLOCKS], g_blkB[DET_BLOCKS];
__device__ unsigned g_w1h[BR * 128], g_w3h[BR * 128];   // half2-packed, word-permuted

// word permutation within 8-word (k16) group: orig word tg -> pos 2tg, tg+4 -> 2tg+1
__host__ __device__ __forceinline__ int wperm(int w) {
    return (w & ~7) | ((w & 3) << 1) | ((w >> 2) & 1);
}

__device__ __forceinline__ unsigned packh2(float lo, float hi) {
    __half2 h = __floats2half2_rn(lo, hi);
    return *reinterpret_cast<unsigned*>(&h);
}

// mish(x) = x * tanh(softplus(x)) = x * (z^2-1)/(z^2+1), z = 1+exp(x)
__device__ __forceinline__ float mishf(float x) {
    if (x > 30.f) return x;
    float z = 1.f + __expf(x);
    float z2 = z * z;
    return x * __fdividef(z2 - 1.f, z2 + 1.f);
}

__device__ __forceinline__ void mma16(float* c, const unsigned* a, unsigned b0, unsigned b1) {
    asm volatile(
        "mma.sync.aligned.m16n8k16.row.col.f32.f16.f16.f32 "
        "{%0,%1,%2,%3}, {%4,%5,%6,%7}, {%8,%9}, {%0,%1,%2,%3};\n"
        : "+f"(c[0]), "+f"(c[1]), "+f"(c[2]), "+f"(c[3])
        : "r"(a[0]), "r"(a[1]), "r"(a[2]), "r"(a[3]), "r"(b0), "r"(b1));
}

// ------- mask dtype detection + W1/W3 fp16 convert+permute -------
// int32 layout: bytes at i%4!=0 are all zero.
// float32 layout (0.0f/1.0f): bytes at i%4==0 are all zero.
// uint8/bool layout: both groups contain nonzero bytes.
__global__ void detect_kernel(const unsigned char* __restrict__ m,
                              const float* __restrict__ w1,
                              const float* __restrict__ w3) {
    unsigned a = 0, b = 0;
    const int stride = DET_BLOCKS * 256;
    for (int i = blockIdx.x * 256 + threadIdx.x; i < BATCH * LLEN; i += stride) {
        unsigned v = m[i];
        if ((i & 3) == 0) a |= v; else b |= v;
    }
    a = __reduce_or_sync(0xffffffffu, a);
    b = __reduce_or_sync(0xffffffffu, b);
    __shared__ unsigned sa[8], sb[8];
    int w = threadIdx.x >> 5;
    if ((threadIdx.x & 31) == 0) { sa[w] = a; sb[w] = b; }
    __syncthreads();
    if (threadIdx.x == 0) {
        unsigned A = 0, B = 0;
        #pragma unroll
        for (int i = 0; i < 8; i++) { A |= sa[i]; B |= sb[i]; }
        g_blkA[blockIdx.x] = A; g_blkB[blockIdx.x] = B;
    }
    // convert + word-permute weights: word w holds k=2w,2w+1 as half2
    for (int i = blockIdx.x * 256 + threadIdx.x; i < BR * 128; i += stride) {
        int row = i >> 7, w2i = i & 127;
        int wp = wperm(w2i);
        g_w1h[(row << 7) + wp] = packh2(w1[row * 256 + 2 * w2i], w1[row * 256 + 2 * w2i + 1]);
        g_w3h[(row << 7) + wp] = packh2(w3[row * 256 + 2 * w2i], w3[row * 256 + 2 * w2i + 1]);
    }
}

// ---------------- fused main kernel ----------------
__global__ void __launch_bounds__(NTHREADS, 4) fused_kernel(
    const float* __restrict__ x, const void* __restrict__ mk,
    const float* __restrict__ b1w, const float* __restrict__ b1b,
    const float* __restrict__ b1m, const float* __restrict__ b1v,
    const float* __restrict__ b2w, const float* __restrict__ b2b,
    const float* __restrict__ b2m, const float* __restrict__ b2v,
    const float* __restrict__ b3w, const float* __restrict__ b3b,
    const float* __restrict__ b3m, const float* __restrict__ b3v,
    const float* __restrict__ w2,
    float* __restrict__ out)
{
    extern __shared__ unsigned smem[];
    unsigned* sB = smem;                        // [NCOL][SBW] fp16 tile (X2 -> Y1 -> Y2)
    __half* sBh = (__half*)sB;
    __shared__ float sS1[BR], sT1[BR], sS2[BR], sT2[BR], sS3[BR], sT3[BR];
    __shared__ float sWa[BR], sWb[BR], sWc[BR];
    __shared__ unsigned char sMk[NCOL + 4];
    __shared__ int sMode;

    const int tid = threadIdx.x;
    const int bb = blockIdx.y;
    const int l0 = blockIdx.x * TN;

    // mask dtype mode (reduce detect blocks' partials)
    if (tid < 32) {
        unsigned A = 0, B = 0;
        for (int i = tid; i < DET_BLOCKS; i += 32) { A |= g_blkA[i]; B |= g_blkB[i]; }
        A = __reduce_or_sync(0xffffffffu, A);
        B = __reduce_or_sync(0xffffffffu, B);
        if (tid == 0) sMode = (A == 0) ? 2 : ((B == 0) ? 0 : 1);
    }
    // per-channel fused BN constants + conv weights
    {
        int ch = tid;
        float i1 = rsqrtf(b1v[ch] + BN_EPS); float s1 = b1w[ch] * i1;
        sS1[ch] = s1; sT1[ch] = b1b[ch] - s1 * b1m[ch];
        float i2 = rsqrtf(b2v[ch] + BN_EPS); float s2 = b2w[ch] * i2;
        sS2[ch] = s2; sT2[ch] = b2b[ch] - s2 * b2m[ch];
        float i3 = rsqrtf(b3v[ch] + BN_EPS); float s3 = b3w[ch] * i3;
        sS3[ch] = s3; sT3[ch] = b3b[ch] - s3 * b3m[ch];
        sWa[ch] = w2[ch * 3 + 0]; sWb[ch] = w2[ch * 3 + 1]; sWc[ch] = w2[ch * 3 + 2];
    }

    // load X2 tile (cols l0-1 .. l0+62): pack k-pairs to fp16, word-permuted
    {
        const float* xb = x + ((size_t)bb * CTOT + BR) * LLEN;
        #pragma unroll 4
        for (int idx = tid; idx < 128 * NCOL; idx += NTHREADS) {
            int w = idx >> 6, n = idx & 63;
            int l = l0 - 1 + n;
            float v0 = 0.f, v1 = 0.f;
            if (l >= 0 && l < LLEN) {
                const float* p = xb + (size_t)(2 * w) * LLEN + l;
                v0 = p[0]; v1 = p[LLEN];
            }
            sB[n * SBW + wperm(w)] = packh2(v0, v1);
        }
    }
    // copy x1 into odd output channels (independent work)
    {
        const float* x1b = x + (size_t)bb * CTOT * LLEN;
        float* ob = out + (size_t)bb * CTOT * LLEN;
        #pragma unroll 4
        for (int idx = tid; idx < BR * NCOL; idx += NTHREADS) {
            int r = idx >> 6, c = idx & 63;
            int l = l0 + c;
            if (c < TN && l < LLEN)
                ob[(size_t)(2 * r + 1) * LLEN + l] = x1b[(size_t)r * LLEN + l];
        }
    }
    __syncthreads();

    // fill per-tile mask bytes (needs sMode; consumed after next sync)
    if (tid < NCOL + 4) {
        int l = l0 - 1 + tid;
        unsigned char v = 0;
        if (tid < NCOL && l >= 0 && l < LLEN) {
            int mode = sMode;
            size_t i = (size_t)bb * LLEN + l;
            if (mode == 0)      v = (((const int*)mk)[i] != 0);
            else if (mode == 1) v = (((const unsigned char*)mk)[i] != 0);
            else                v = (((const float*)mk)[i] != 0.f);
        }
        sMk[tid] = v;
    }

    const int warp = tid >> 5, lane = tid & 31;
    const int g = lane >> 2, tg = lane & 3;
    const int m0 = warp * 32;
    const int rows4[4] = { m0 + g, m0 + g + 8, m0 + 16 + g, m0 + 24 + g };
    const int ro[4] = { rows4[0] << 7, rows4[1] << 7, rows4[2] << 7, rows4[3] << 7 };
    // half-index offsets for in-place fp16 Y1 writes (per row)
    int hofr[4];
    #pragma unroll
    for (int q = 0; q < 4; q++) hofr[q] = wperm(rows4[q] >> 1) * 2 + (rows4[q] & 1);

    float acc[2][4][4];    // [mt][nt-in-half][q] — 32 accumulators

    // ================ GEMM1: Y1 = W1 @ X2, two N-halves, fp16 in-place ================
    #pragma unroll
    for (int h = 0; h < 2; h++) {
        #pragma unroll
        for (int mt = 0; mt < 2; mt++)
            #pragma unroll
            for (int nt = 0; nt < 4; nt++)
                #pragma unroll
                for (int q = 0; q < 4; q++) acc[mt][nt][q] = 0.f;
        {
            const unsigned* wb = g_w1h;
            #pragma unroll
            for (int it = 0; it < 16; it++) {
                const int kw = it * 8 + 2 * tg;
                uint2 A0 = *(const uint2*)&wb[ro[0] + kw];
                uint2 A1 = *(const uint2*)&wb[ro[1] + kw];
                uint2 A2 = *(const uint2*)&wb[ro[2] + kw];
                uint2 A3 = *(const uint2*)&wb[ro[3] + kw];
                unsigned a0[4] = { A0.x, A1.x, A0.y, A1.y };
                unsigned a1[4] = { A2.x, A3.x, A2.y, A3.y };
                #pragma unroll
                for (int nt = 0; nt < 4; nt++) {
                    uint2 Bv = *(const uint2*)&sB[((h * 4 + nt) * 8 + g) * SBW + kw];
                    mma16(acc[0][nt], a0, Bv.x, Bv.y);
                    mma16(acc[1][nt], a1, Bv.x, Bv.y);
                }
            }
        }
        __syncthreads();   // all warps done reading this half's cols
        // epilogue: mish + bn1 + mask -> fp16, in place over this half's cols
        {
            float sv[4], tv[4];
            #pragma unroll
            for (int q = 0; q < 4; q++) { sv[q] = sS1[rows4[q]]; tv[q] = sT1[rows4[q]]; }
            #pragma unroll
            for (int mt = 0; mt < 2; mt++)
                #pragma unroll
                for (int nt = 0; nt < 4; nt++)
                    #pragma unroll
                    for (int q = 0; q < 4; q++) {
                        int ri = mt * 2 + (q >> 1);
                        int col = (h * 4 + nt) * 8 + 2 * tg + (q & 1);
                        float y = mishf(acc[mt][nt][q]);
                        float z = sv[ri] * y + tv[ri];
                        sBh[col * (2 * SBW) + hofr[ri]] =
                            __float2half_rn(sMk[col] ? z : 0.f);
                    }
        }
    }
    __syncthreads();   // epi of half 1 visible to all

    // ------- depthwise conv3 + bn2 + mask, in place (thread owns its channel) -------
    // NOTE: cols 62,63 keep stale Y1 after this; GEMM3 computes garbage there but
    // epilogue-3 never stores those columns (c0 <= 60), so no zeroing is needed —
    // zeroing here raced with other threads' conv reads of cols 62/63 (R6 bug).
    {
        int ch = tid;
        float wa = sWa[ch], wb_ = sWb[ch], wc = sWc[ch];
        float s2 = sS2[ch], t2 = sT2[ch];
        const int hoff = wperm(ch >> 1) * 2 + (ch & 1);
        float p0 = __half2float(sBh[0 * (2 * SBW) + hoff]);
        float p1 = __half2float(sBh[1 * (2 * SBW) + hoff]);
        #pragma unroll 2
        for (int j = 0; j < TN; j++) {
            float p2 = __half2float(sBh[(j + 2) * (2 * SBW) + hoff]);
            float c = wa * p0 + wb_ * p1 + wc * p2;
            float v = sMk[j + 1] ? (s2 * c + t2) : 0.f;
            sBh[j * (2 * SBW) + hoff] = __float2half_rn(v);  // safe: sliding window
            p0 = p1; p1 = p2;
        }
    }
    __syncthreads();

    // ================ GEMM3: O = W3 @ Y2, two N-halves, direct global ================
    {
        float* ob = out + (size_t)bb * CTOT * LLEN;
        #pragma unroll
        for (int h = 0; h < 2; h++) {
            #pragma unroll
            for (int mt = 0; mt < 2; mt++)
                #pragma unroll
                for (int nt = 0; nt < 4; nt++)
                    #pragma unroll
                    for (int q = 0; q < 4; q++) acc[mt][nt][q] = 0.f;
            {
                const unsigned* wb = g_w3h;
                #pragma unroll
                for (int it = 0; it < 16; it++) {
                    const int kw = it * 8 + 2 * tg;
                    uint2 A0 = *(const uint2*)&wb[ro[0] + kw];
                    uint2 A1 = *(const uint2*)&wb[ro[1] + kw];
                    uint2 A2 = *(const uint2*)&wb[ro[2] + kw];
                    uint2 A3 = *(const uint2*)&wb[ro[3] + kw];
                    unsigned a0[4] = { A0.x, A1.x, A0.y, A1.y };
                    unsigned a1[4] = { A2.x, A3.x, A2.y, A3.y };
                    #pragma unroll
                    for (int nt = 0; nt < 4; nt++) {
                        uint2 Bv = *(const uint2*)&sB[((h * 4 + nt) * 8 + g) * SBW + kw];
                        mma16(acc[0][nt], a0, Bv.x, Bv.y);
                        mma16(acc[1][nt], a1, Bv.x, Bv.y);
                    }
                }
            }
            // epilogue: mish + bn3 + mask -> even output channels, STG.64 pairs
            {
                float sv[4], tv[4];
                #pragma unroll
                for (int q = 0; q < 4; q++) { sv[q] = sS3[rows4[q]]; tv[q] = sT3[rows4[q]]; }
                #pragma unroll
                for (int mt = 0; mt < 2; mt++)
                    #pragma unroll
                    for (int nt = 0; nt < 4; nt++)
                        #pragma unroll
                        for (int qp = 0; qp < 2; qp++) {
                            int ri = mt * 2 + qp;
                            int c0 = (h * 4 + nt) * 8 + 2 * tg;
                            int l = l0 + c0;
                            if (c0 < TN - 1 && l + 1 < LLEN) {
                                float y0 = mishf(acc[mt][nt][2 * qp + 0]);
                                float y1 = mishf(acc[mt][nt][2 * qp + 1]);
                                float z0 = sv[ri] * y0 + tv[ri];
                                float z1 = sv[ri] * y1 + tv[ri];
                                float2 zz;
                                zz.x = sMk[c0 + 1] ? z0 : 0.f;
                                zz.y = sMk[c0 + 2] ? z1 : 0.f;
                                *(float2*)&ob[(size_t)(2 * rows4[ri]) * LLEN + l] = zz;
                            }
                        }
            }
        }
    }
}

// ---------------- launch ----------------
extern "C" void kernel_launch(void* const* d_in, const int* in_sizes, int n_in,
                              void* d_out, int out_size) {
    (void)in_sizes; (void)n_in; (void)out_size;
    const float* x   = (const float*)d_in[0];
    const void*  mk  = d_in[1];
    const float* w1  = (const float*)d_in[2];
    const float* w2  = (const float*)d_in[3];
    const float* w3  = (const float*)d_in[4];
    const float* b1w = (const float*)d_in[5];
    const float* b1b = (const float*)d_in[6];
    const float* b1m = (const float*)d_in[7];
    const float* b1v = (const float*)d_in[8];
    const float* b2w = (const float*)d_in[9];
    const float* b2b = (const float*)d_in[10];
    const float* b2m = (const float*)d_in[11];
    const float* b2v = (const float*)d_in[12];
    const float* b3w = (const float*)d_in[13];
    const float* b3b = (const float*)d_in[14];
    const float* b3m = (const float*)d_in[15];
    const float* b3v = (const float*)d_in[16];
    float* out = (float*)d_out;

    const int smem_bytes = NCOL * SBW * (int)sizeof(unsigned);
    cudaFuncSetAttribute(fused_kernel, cudaFuncAttributeMaxDynamicSharedMemorySize, smem_bytes);

    detect_kernel<<<DET_BLOCKS, 256>>>((const unsigned char*)mk, w1, w3);

    dim3 grid(LTILES, BATCH);
    fused_kernel<<<grid, NTHREADS, smem_bytes>>>(
        x, mk,
        b1w, b1b, b1m, b1v,
        b2w, b2b, b2m, b2v,
        b3w, b3b, b3m, b3v,
        w2, out);
}

// round 9
// speedup vs baseline: 4.6022x; 1.0559x over previous
#include <cuda_runtime.h>
#include <cuda_fp16.h>
#include <cstdint>
#include <cstddef>

#define BATCH 32
#define CTOT 512
#define BR 256
#define LLEN 4096
#define TN 62            // output columns per tile
#define NCOL 64          // TN + 2 halo columns
#define SBW 136          // fp16 B-tile col stride in 32-bit words (≡8 mod 32)
#define NTHREADS 256
#define LTILES 67        // ceil(4096/62)
#define BN_EPS 1e-5f
#define DET_BLOCKS 128

// ---------------- device scratch (allocation-free) ----------------
__device__ unsigned g_blkA[DET_BLOCKS], g_blkB[DET_BLOCKS];
// fragment-major weight images: [wb(8)][it(16)][lane(32)][8 words], fully coalesced
__device__ unsigned g_w1f[8 * 16 * 32 * 8], g_w3f[8 * 16 * 32 * 8];

// word permutation within 8-word (k16) group (B tile): orig word tg -> 2tg, tg+4 -> 2tg+1
__host__ __device__ __forceinline__ int wperm(int w) {
    return (w & ~7) | ((w & 3) << 1) | ((w >> 2) & 1);
}

__device__ __forceinline__ unsigned packh2(float lo, float hi) {
    __half2 h = __floats2half2_rn(lo, hi);
    return *reinterpret_cast<unsigned*>(&h);
}

// mish(x) = x * tanh(softplus(x)) = x * (z^2-1)/(z^2+1), z = 1+exp(x)
__device__ __forceinline__ float mishf(float x) {
    if (x > 30.f) return x;
    float z = 1.f + __expf(x);
    float z2 = z * z;
    return x * __fdividef(z2 - 1.f, z2 + 1.f);
}

__device__ __forceinline__ void mma16(float* c, const unsigned* a, unsigned b0, unsigned b1) {
    asm volatile(
        "mma.sync.aligned.m16n8k16.row.col.f32.f16.f16.f32 "
        "{%0,%1,%2,%3}, {%4,%5,%6,%7}, {%8,%9}, {%0,%1,%2,%3};\n"
        : "+f"(c[0]), "+f"(c[1]), "+f"(c[2]), "+f"(c[3])
        : "r"(a[0]), "r"(a[1]), "r"(a[2]), "r"(a[3]), "r"(b0), "r"(b1));
}

// ------- mask dtype detection + fragment-major fp16 weight image build -------
// int32 layout: bytes at i%4!=0 are all zero.
// float32 layout (0.0f/1.0f): bytes at i%4==0 are all zero.
// uint8/bool layout: both groups contain nonzero bytes.
__global__ void detect_kernel(const unsigned char* __restrict__ m,
                              const float* __restrict__ w1,
                              const float* __restrict__ w3) {
    unsigned a = 0, b = 0;
    const int stride = DET_BLOCKS * 256;
    int gtid = blockIdx.x * 256 + threadIdx.x;
    for (int i = gtid; i < BATCH * LLEN; i += stride) {
        unsigned v = m[i];
        if ((i & 3) == 0) a |= v; else b |= v;
    }
    a = __reduce_or_sync(0xffffffffu, a);
    b = __reduce_or_sync(0xffffffffu, b);
    __shared__ unsigned sa[8], sb[8];
    int w = threadIdx.x >> 5;
    if ((threadIdx.x & 31) == 0) { sa[w] = a; sb[w] = b; }
    __syncthreads();
    if (threadIdx.x == 0) {
        unsigned A = 0, B = 0;
        #pragma unroll
        for (int i = 0; i < 8; i++) { A |= sa[i]; B |= sb[i]; }
        g_blkA[blockIdx.x] = A; g_blkB[blockIdx.x] = B;
    }
    // fragment-major image: i = ((wb*16+it)*32+lane)*8 + j
    // j>>1 selects row q (rows4[q] = wb*32 + g + q*8); j&1 selects word tg / tg+4
    for (int i = gtid; i < 32768; i += stride) {
        int j = i & 7, lane = (i >> 3) & 31, it = (i >> 8) & 15, wb_ = i >> 12;
        int g = lane >> 2, tg = lane & 3;
        int q = j >> 1;
        int row = wb_ * 32 + g + q * 8;
        int wo = it * 8 + tg + ((j & 1) ? 4 : 0);
        int k0 = 2 * wo;
        g_w1f[i] = packh2(w1[row * 256 + k0], w1[row * 256 + k0 + 1]);
        g_w3f[i] = packh2(w3[row * 256 + k0], w3[row * 256 + k0 + 1]);
    }
}

// ---------------- fused main kernel ----------------
__global__ void __launch_bounds__(NTHREADS, 2) fused_kernel(
    const float* __restrict__ x, const void* __restrict__ mk,
    const float* __restrict__ b1w, const float* __restrict__ b1b,
    const float* __restrict__ b1m, const float* __restrict__ b1v,
    const float* __restrict__ b2w, const float* __restrict__ b2b,
    const float* __restrict__ b2m, const float* __restrict__ b2v,
    const float* __restrict__ b3w, const float* __restrict__ b3b,
    const float* __restrict__ b3m, const float* __restrict__ b3v,
    const float* __restrict__ w2,
    float* __restrict__ out)
{
    extern __shared__ unsigned smem[];
    unsigned* sB = smem;                        // [NCOL][SBW] fp16 tile (X2 -> Y1 -> Y2)
    __half* sBh = (__half*)sB;
    __shared__ float sS1[BR], sT1[BR], sS2[BR], sT2[BR], sS3[BR], sT3[BR];
    __shared__ float sWa[BR], sWb[BR], sWc[BR];
    __shared__ unsigned char sMk[NCOL + 4];
    __shared__ int sMode;

    const int tid = threadIdx.x;
    const int bb = blockIdx.y;
    const int l0 = blockIdx.x * TN;

    // mask dtype mode (reduce detect blocks' partials)
    if (tid < 32) {
        unsigned A = 0, B = 0;
        for (int i = tid; i < DET_BLOCKS; i += 32) { A |= g_blkA[i]; B |= g_blkB[i]; }
        A = __reduce_or_sync(0xffffffffu, A);
        B = __reduce_or_sync(0xffffffffu, B);
        if (tid == 0) sMode = (A == 0) ? 2 : ((B == 0) ? 0 : 1);
    }
    // per-channel fused BN constants + conv weights
    {
        int ch = tid;
        float i1 = rsqrtf(b1v[ch] + BN_EPS); float s1 = b1w[ch] * i1;
        sS1[ch] = s1; sT1[ch] = b1b[ch] - s1 * b1m[ch];
        float i2 = rsqrtf(b2v[ch] + BN_EPS); float s2 = b2w[ch] * i2;
        sS2[ch] = s2; sT2[ch] = b2b[ch] - s2 * b2m[ch];
        float i3 = rsqrtf(b3v[ch] + BN_EPS); float s3 = b3w[ch] * i3;
        sS3[ch] = s3; sT3[ch] = b3b[ch] - s3 * b3m[ch];
        sWa[ch] = w2[ch * 3 + 0]; sWb[ch] = w2[ch * 3 + 1]; sWc[ch] = w2[ch * 3 + 2];
    }

    // load X2 tile (cols l0-1 .. l0+62): pack k-pairs to fp16, word-permuted
    {
        const float* xb = x + ((size_t)bb * CTOT + BR) * LLEN;
        #pragma unroll 4
        for (int idx = tid; idx < 128 * NCOL; idx += NTHREADS) {
            int w = idx >> 6, n = idx & 63;
            int l = l0 - 1 + n;
            float v0 = 0.f, v1 = 0.f;
            if (l >= 0 && l < LLEN) {
                const float* p = xb + (size_t)(2 * w) * LLEN + l;
                v0 = p[0]; v1 = p[LLEN];
            }
            sB[n * SBW + wperm(w)] = packh2(v0, v1);
        }
    }
    // copy x1 into odd output channels (independent work)
    {
        const float* x1b = x + (size_t)bb * CTOT * LLEN;
        float* ob = out + (size_t)bb * CTOT * LLEN;
        #pragma unroll 4
        for (int idx = tid; idx < BR * NCOL; idx += NTHREADS) {
            int r = idx >> 6, c = idx & 63;
            int l = l0 + c;
            if (c < TN && l < LLEN)
                ob[(size_t)(2 * r + 1) * LLEN + l] = x1b[(size_t)r * LLEN + l];
        }
    }
    __syncthreads();

    // fill per-tile mask bytes (needs sMode; consumed after next sync)
    if (tid < NCOL + 4) {
        int l = l0 - 1 + tid;
        unsigned char v = 0;
        if (tid < NCOL && l >= 0 && l < LLEN) {
            int mode = sMode;
            size_t i = (size_t)bb * LLEN + l;
            if (mode == 0)      v = (((const int*)mk)[i] != 0);
            else if (mode == 1) v = (((const unsigned char*)mk)[i] != 0);
            else                v = (((const float*)mk)[i] != 0.f);
        }
        sMk[tid] = v;
    }

    const int warp = tid >> 5, lane = tid & 31;
    const int g = lane >> 2, tg = lane & 3;
    const int m0 = warp * 32;
    const int rows4[4] = { m0 + g, m0 + g + 8, m0 + 16 + g, m0 + 24 + g };
    // fragment-major A base: wb*4096 + lane*8 (per it: +256 words)
    const int abase = warp * 4096 + lane * 8;
    // half-index offsets for in-place fp16 Y1 writes (per row)
    int hofr[4];
    #pragma unroll
    for (int q = 0; q < 4; q++) hofr[q] = wperm(rows4[q] >> 1) * 2 + (rows4[q] & 1);

    float acc[2][8][4];    // 64 accumulators

    // ================ GEMM1: Y1 = W1 @ X2 (coalesced A frags) ================
    #pragma unroll
    for (int mt = 0; mt < 2; mt++)
        #pragma unroll
        for (int nt = 0; nt < 8; nt++)
            #pragma unroll
            for (int q = 0; q < 4; q++) acc[mt][nt][q] = 0.f;
    {
        const unsigned* wp = g_w1f + abase;
        #pragma unroll
        for (int it = 0; it < 16; it++) {
            uint4 q1 = *(const uint4*)(wp + it * 256);
            uint4 q2 = *(const uint4*)(wp + it * 256 + 4);
            unsigned a0[4] = { q1.x, q1.z, q1.y, q1.w };
            unsigned a1[4] = { q2.x, q2.z, q2.y, q2.w };
            const int kw = it * 8 + 2 * tg;
            #pragma unroll
            for (int nt = 0; nt < 8; nt++) {
                uint2 Bv = *(const uint2*)&sB[(nt * 8 + g) * SBW + kw];
                mma16(acc[0][nt], a0, Bv.x, Bv.y);
                mma16(acc[1][nt], a1, Bv.x, Bv.y);
            }
        }
    }
    __syncthreads();   // all warps done reading X2 tile
    // epilogue 1: mish + bn1 + mask -> fp16, in place
    {
        float sv[4], tv[4];
        #pragma unroll
        for (int q = 0; q < 4; q++) { sv[q] = sS1[rows4[q]]; tv[q] = sT1[rows4[q]]; }
        #pragma unroll
        for (int mt = 0; mt < 2; mt++)
            #pragma unroll
            for (int nt = 0; nt < 8; nt++)
                #pragma unroll
                for (int q = 0; q < 4; q++) {
                    int ri = mt * 2 + (q >> 1);
                    int col = nt * 8 + 2 * tg + (q & 1);
                    float y = mishf(acc[mt][nt][q]);
                    float z = sv[ri] * y + tv[ri];
                    sBh[col * (2 * SBW) + hofr[ri]] =
                        __float2half_rn(sMk[col] ? z : 0.f);
                }
    }
    __syncthreads();

    // ------- depthwise conv3 + bn2 + mask, in place (thread owns its channel) -------
    // cols 62,63 keep stale Y1; GEMM3 garbage there is never stored (c0 <= 60).
    {
        int ch = tid;
        float wa = sWa[ch], wb_ = sWb[ch], wc = sWc[ch];
        float s2 = sS2[ch], t2 = sT2[ch];
        const int hoff = wperm(ch >> 1) * 2 + (ch & 1);
        float p0 = __half2float(sBh[0 * (2 * SBW) + hoff]);
        float p1 = __half2float(sBh[1 * (2 * SBW) + hoff]);
        #pragma unroll 2
        for (int j = 0; j < TN; j++) {
            float p2 = __half2float(sBh[(j + 2) * (2 * SBW) + hoff]);
            float c = wa * p0 + wb_ * p1 + wc * p2;
            float v = sMk[j + 1] ? (s2 * c + t2) : 0.f;
            sBh[j * (2 * SBW) + hoff] = __float2half_rn(v);  // safe: sliding window
            p0 = p1; p1 = p2;
        }
    }
    __syncthreads();

    // ================ GEMM3: O = W3 @ Y2 ================
    #pragma unroll
    for (int mt = 0; mt < 2; mt++)
        #pragma unroll
        for (int nt = 0; nt < 8; nt++)
            #pragma unroll
            for (int q = 0; q < 4; q++) acc[mt][nt][q] = 0.f;
    {
        const unsigned* wp = g_w3f + abase;
        #pragma unroll
        for (int it = 0; it < 16; it++) {
            uint4 q1 = *(const uint4*)(wp + it * 256);
            uint4 q2 = *(const uint4*)(wp + it * 256 + 4);
            unsigned a0[4] = { q1.x, q1.z, q1.y, q1.w };
            unsigned a1[4] = { q2.x, q2.z, q2.y, q2.w };
            const int kw = it * 8 + 2 * tg;
            #pragma unroll
            for (int nt = 0; nt < 8; nt++) {
                uint2 Bv = *(const uint2*)&sB[(nt * 8 + g) * SBW + kw];
                mma16(acc[0][nt], a0, Bv.x, Bv.y);
                mma16(acc[1][nt], a1, Bv.x, Bv.y);
            }
        }
    }
    // epilogue 3: mish + bn3 + mask -> even output channels, STG.64 pairs
    {
        float sv[4], tv[4];
        #pragma unroll
        for (int q = 0; q < 4; q++) { sv[q] = sS3[rows4[q]]; tv[q] = sT3[rows4[q]]; }
        float* ob = out + (size_t)bb * CTOT * LLEN;
        #pragma unroll
        for (int mt = 0; mt < 2; mt++)
            #pragma unroll
            for (int nt = 0; nt < 8; nt++)
                #pragma unroll
                for (int qp = 0; qp < 2; qp++) {
                    int ri = mt * 2 + qp;
                    int c0 = nt * 8 + 2 * tg;
                    int l = l0 + c0;
                    if (c0 < TN - 1 && l + 1 < LLEN) {
                        float y0 = mishf(acc[mt][nt][2 * qp + 0]);
                        float y1 = mishf(acc[mt][nt][2 * qp + 1]);
                        float z0 = sv[ri] * y0 + tv[ri];
                        float z1 = sv[ri] * y1 + tv[ri];
                        float2 zz;
                        zz.x = sMk[c0 + 1] ? z0 : 0.f;
                        zz.y = sMk[c0 + 2] ? z1 : 0.f;
                        *(float2*)&ob[(size_t)(2 * rows4[ri]) * LLEN + l] = zz;
                    }
                }
    }
}

// ---------------- launch ----------------
extern "C" void kernel_launch(void* const* d_in, const int* in_sizes, int n_in,
                              void* d_out, int out_size) {
    (void)in_sizes; (void)n_in; (void)out_size;
    const float* x   = (const float*)d_in[0];
    const void*  mk  = d_in[1];
    const float* w1  = (const float*)d_in[2];
    const float* w2  = (const float*)d_in[3];
    const float* w3  = (const float*)d_in[4];
    const float* b1w = (const float*)d_in[5];
    const float* b1b = (const float*)d_in[6];
    const float* b1m = (const float*)d_in[7];
    const float* b1v = (const float*)d_in[8];
    const float* b2w = (const float*)d_in[9];
    const float* b2b = (const float*)d_in[10];
    const float* b2m = (const float*)d_in[11];
    const float* b2v = (const float*)d_in[12];
    const float* b3w = (const float*)d_in[13];
    const float* b3b = (const float*)d_in[14];
    const float* b3m = (const float*)d_in[15];
    const float* b3v = (const float*)d_in[16];
    float* out = (float*)d_out;

    const int smem_bytes = NCOL * SBW * (int)sizeof(unsigned);
    cudaFuncSetAttribute(fused_kernel, cudaFuncAttributeMaxDynamicSharedMemorySize, smem_bytes);

    detect_kernel<<<DET_BLOCKS, 256>>>((const unsigned char*)mk, w1, w3);

    dim3 grid(LTILES, BATCH);
    fused_kernel<<<grid, NTHREADS, smem_bytes>>>(
        x, mk,
        b1w, b1b, b1m, b1v,
        b2w, b2b, b2m, b2v,
        b3w, b3b, b3m, b3v,
        w2, out);
}

// round 10
// speedup vs baseline: 5.3982x; 1.1729x over previous
#include <cuda_runtime.h>
#include <cuda_fp16.h>
#include <cstdint>
#include <cstddef>

#define BATCH 32
#define CTOT 512
#define BR 256
#define LLEN 4096
#define TN 62            // output columns per tile
#define NCOL 64          // TN + 2 halo columns
#define SBW 136          // fp16 B-tile col stride in 32-bit words (≡8 mod 32)
#define NTHREADS 256
#define LTILES 67        // ceil(4096/62)
#define BN_EPS 1e-5f
#define DET_BLOCKS 128

// ---------------- device scratch (allocation-free) ----------------
__device__ unsigned g_blkA[DET_BLOCKS], g_blkB[DET_BLOCKS];
// fragment-major weight images: [wb(8)][it(16)][lane(32)][8 words], fully coalesced
__device__ unsigned g_w1f[8 * 16 * 32 * 8], g_w3f[8 * 16 * 32 * 8];

// word permutation within 8-word (k16) group (B tile): orig word tg -> 2tg, tg+4 -> 2tg+1
__host__ __device__ __forceinline__ int wperm(int w) {
    return (w & ~7) | ((w & 3) << 1) | ((w >> 2) & 1);
}

__device__ __forceinline__ unsigned packh2(float lo, float hi) {
    __half2 h = __floats2half2_rn(lo, hi);
    return *reinterpret_cast<unsigned*>(&h);
}

// mish(x) = x * tanh(softplus(x)) = x * (z^2-1)/(z^2+1), z = 1+exp(x)
__device__ __forceinline__ float mishf(float x) {
    if (x > 30.f) return x;
    float z = 1.f + __expf(x);
    float z2 = z * z;
    return x * __fdividef(z2 - 1.f, z2 + 1.f);
}

__device__ __forceinline__ void mma16(float* c, const unsigned* a, unsigned b0, unsigned b1) {
    asm volatile(
        "mma.sync.aligned.m16n8k16.row.col.f32.f16.f16.f32 "
        "{%0,%1,%2,%3}, {%4,%5,%6,%7}, {%8,%9}, {%0,%1,%2,%3};\n"
        : "+f"(c[0]), "+f"(c[1]), "+f"(c[2]), "+f"(c[3])
        : "r"(a[0]), "r"(a[1]), "r"(a[2]), "r"(a[3]), "r"(b0), "r"(b1));
}

// ------- mask dtype detection + fragment-major fp16 weight image build -------
// int32 layout: bytes at i%4!=0 are all zero.
// float32 layout (0.0f/1.0f): bytes at i%4==0 are all zero.
// uint8/bool layout: both groups contain nonzero bytes.
__global__ void detect_kernel(const unsigned char* __restrict__ m,
                              const float* __restrict__ w1,
                              const float* __restrict__ w3) {
    unsigned a = 0, b = 0;
    const int stride = DET_BLOCKS * 256;
    int gtid = blockIdx.x * 256 + threadIdx.x;
    for (int i = gtid; i < BATCH * LLEN; i += stride) {
        unsigned v = m[i];
        if ((i & 3) == 0) a |= v; else b |= v;
    }
    a = __reduce_or_sync(0xffffffffu, a);
    b = __reduce_or_sync(0xffffffffu, b);
    __shared__ unsigned sa[8], sb[8];
    int w = threadIdx.x >> 5;
    if ((threadIdx.x & 31) == 0) { sa[w] = a; sb[w] = b; }
    __syncthreads();
    if (threadIdx.x == 0) {
        unsigned A = 0, B = 0;
        #pragma unroll
        for (int i = 0; i < 8; i++) { A |= sa[i]; B |= sb[i]; }
        g_blkA[blockIdx.x] = A; g_blkB[blockIdx.x] = B;
    }
    // fragment-major image: i = ((wb*16+it)*32+lane)*8 + j
    // j>>1 selects row q (rows4[q] = wb*32 + g + q*8); j&1 selects word tg / tg+4
    for (int i = gtid; i < 32768; i += stride) {
        int j = i & 7, lane = (i >> 3) & 31, it = (i >> 8) & 15, wb_ = i >> 12;
        int g = lane >> 2, tg = lane & 3;
        int q = j >> 1;
        int row = wb_ * 32 + g + q * 8;
        int wo = it * 8 + tg + ((j & 1) ? 4 : 0);
        int k0 = 2 * wo;
        g_w1f[i] = packh2(w1[row * 256 + k0], w1[row * 256 + k0 + 1]);
        g_w3f[i] = packh2(w3[row * 256 + k0], w3[row * 256 + k0 + 1]);
    }
}

// ---------------- fused main kernel ----------------
__global__ void __launch_bounds__(NTHREADS, 4) fused_kernel(
    const float* __restrict__ x, const void* __restrict__ mk,
    const float* __restrict__ b1w, const float* __restrict__ b1b,
    const float* __restrict__ b1m, const float* __restrict__ b1v,
    const float* __restrict__ b2w, const float* __restrict__ b2b,
    const float* __restrict__ b2m, const float* __restrict__ b2v,
    const float* __restrict__ b3w, const float* __restrict__ b3b,
    const float* __restrict__ b3m, const float* __restrict__ b3v,
    const float* __restrict__ w2,
    float* __restrict__ out)
{
    extern __shared__ unsigned smem[];
    unsigned* sB = smem;                        // [NCOL][SBW] fp16 tile (X2 -> Y1 -> Y2)
    __half* sBh = (__half*)sB;
    __shared__ float sS1[BR], sT1[BR], sS2[BR], sT2[BR], sS3[BR], sT3[BR];
    __shared__ float sWa[BR], sWb[BR], sWc[BR];
    __shared__ unsigned char sMk[NCOL + 4];
    __shared__ int sMode;

    const int tid = threadIdx.x;
    const int bb = blockIdx.y;
    const int l0 = blockIdx.x * TN;

    // mask dtype mode (reduce detect blocks' partials)
    if (tid < 32) {
        unsigned A = 0, B = 0;
        for (int i = tid; i < DET_BLOCKS; i += 32) { A |= g_blkA[i]; B |= g_blkB[i]; }
        A = __reduce_or_sync(0xffffffffu, A);
        B = __reduce_or_sync(0xffffffffu, B);
        if (tid == 0) sMode = (A == 0) ? 2 : ((B == 0) ? 0 : 1);
    }
    // per-channel fused BN constants + conv weights
    {
        int ch = tid;
        float i1 = rsqrtf(b1v[ch] + BN_EPS); float s1 = b1w[ch] * i1;
        sS1[ch] = s1; sT1[ch] = b1b[ch] - s1 * b1m[ch];
        float i2 = rsqrtf(b2v[ch] + BN_EPS); float s2 = b2w[ch] * i2;
        sS2[ch] = s2; sT2[ch] = b2b[ch] - s2 * b2m[ch];
        float i3 = rsqrtf(b3v[ch] + BN_EPS); float s3 = b3w[ch] * i3;
        sS3[ch] = s3; sT3[ch] = b3b[ch] - s3 * b3m[ch];
        sWa[ch] = w2[ch * 3 + 0]; sWb[ch] = w2[ch * 3 + 1]; sWc[ch] = w2[ch * 3 + 2];
    }

    // load X2 tile (cols l0-1 .. l0+62): pack k-pairs to fp16, word-permuted
    {
        const float* xb = x + ((size_t)bb * CTOT + BR) * LLEN;
        #pragma unroll 4
        for (int idx = tid; idx < 128 * NCOL; idx += NTHREADS) {
            int w = idx >> 6, n = idx & 63;
            int l = l0 - 1 + n;
            float v0 = 0.f, v1 = 0.f;
            if (l >= 0 && l < LLEN) {
                const float* p = xb + (size_t)(2 * w) * LLEN + l;
                v0 = p[0]; v1 = p[LLEN];
            }
            sB[n * SBW + wperm(w)] = packh2(v0, v1);
        }
    }
    // copy x1 into odd output channels (independent work)
    {
        const float* x1b = x + (size_t)bb * CTOT * LLEN;
        float* ob = out + (size_t)bb * CTOT * LLEN;
        #pragma unroll 4
        for (int idx = tid; idx < BR * NCOL; idx += NTHREADS) {
            int r = idx >> 6, c = idx & 63;
            int l = l0 + c;
            if (c < TN && l < LLEN)
                ob[(size_t)(2 * r + 1) * LLEN + l] = x1b[(size_t)r * LLEN + l];
        }
    }
    __syncthreads();

    // fill per-tile mask bytes (needs sMode; consumed after next sync)
    if (tid < NCOL + 4) {
        int l = l0 - 1 + tid;
        unsigned char v = 0;
        if (tid < NCOL && l >= 0 && l < LLEN) {
            int mode = sMode;
            size_t i = (size_t)bb * LLEN + l;
            if (mode == 0)      v = (((const int*)mk)[i] != 0);
            else if (mode == 1) v = (((const unsigned char*)mk)[i] != 0);
            else                v = (((const float*)mk)[i] != 0.f);
        }
        sMk[tid] = v;
    }

    const int warp = tid >> 5, lane = tid & 31;
    const int g = lane >> 2, tg = lane & 3;
    const int m0 = warp * 32;
    const int rows4[4] = { m0 + g, m0 + g + 8, m0 + 16 + g, m0 + 24 + g };
    // fragment-major A base: wb*4096 + lane*8 (per it: +256 words)
    const int abase = warp * 4096 + lane * 8;
    // half-index offsets for in-place fp16 Y1 writes (per row)
    int hofr[4];
    #pragma unroll
    for (int q = 0; q < 4; q++) hofr[q] = wperm(rows4[q] >> 1) * 2 + (rows4[q] & 1);

    float acc[2][4][4];    // [mt][nt-in-half][q] — 32 accumulators

    // ================ GEMM1: Y1 = W1 @ X2, two N-halves, fp16 in-place ================
    #pragma unroll
    for (int h = 0; h < 2; h++) {
        #pragma unroll
        for (int mt = 0; mt < 2; mt++)
            #pragma unroll
            for (int nt = 0; nt < 4; nt++)
                #pragma unroll
                for (int q = 0; q < 4; q++) acc[mt][nt][q] = 0.f;
        {
            const unsigned* wp = g_w1f + abase;
            #pragma unroll
            for (int it = 0; it < 16; it++) {
                uint4 q1 = *(const uint4*)(wp + it * 256);
                uint4 q2 = *(const uint4*)(wp + it * 256 + 4);
                unsigned a0[4] = { q1.x, q1.z, q1.y, q1.w };
                unsigned a1[4] = { q2.x, q2.z, q2.y, q2.w };
                const int kw = it * 8 + 2 * tg;
                #pragma unroll
                for (int nt = 0; nt < 4; nt++) {
                    uint2 Bv = *(const uint2*)&sB[((h * 4 + nt) * 8 + g) * SBW + kw];
                    mma16(acc[0][nt], a0, Bv.x, Bv.y);
                    mma16(acc[1][nt], a1, Bv.x, Bv.y);
                }
            }
        }
        __syncthreads();   // all warps done reading this half's cols
        // epilogue: mish + bn1 + mask -> fp16, in place over this half's cols
        {
            float sv[4], tv[4];
            #pragma unroll
            for (int q = 0; q < 4; q++) { sv[q] = sS1[rows4[q]]; tv[q] = sT1[rows4[q]]; }
            #pragma unroll
            for (int mt = 0; mt < 2; mt++)
                #pragma unroll
                for (int nt = 0; nt < 4; nt++)
                    #pragma unroll
                    for (int q = 0; q < 4; q++) {
                        int ri = mt * 2 + (q >> 1);
                        int col = (h * 4 + nt) * 8 + 2 * tg + (q & 1);
                        float y = mishf(acc[mt][nt][q]);
                        float z = sv[ri] * y + tv[ri];
                        sBh[col * (2 * SBW) + hofr[ri]] =
                            __float2half_rn(sMk[col] ? z : 0.f);
                    }
        }
    }
    __syncthreads();   // epi of half 1 visible to all

    // ------- depthwise conv3 + bn2 + mask, in place (thread owns its channel) -------
    // cols 62,63 keep stale Y1; GEMM3 garbage there is never stored (c0 <= 60).
    {
        int ch = tid;
        float wa = sWa[ch], wb_ = sWb[ch], wc = sWc[ch];
        float s2 = sS2[ch], t2 = sT2[ch];
        const int hoff = wperm(ch >> 1) * 2 + (ch & 1);
        float p0 = __half2float(sBh[0 * (2 * SBW) + hoff]);
        float p1 = __half2float(sBh[1 * (2 * SBW) + hoff]);
        #pragma unroll 2
        for (int j = 0; j < TN; j++) {
            float p2 = __half2float(sBh[(j + 2) * (2 * SBW) + hoff]);
            float c = wa * p0 + wb_ * p1 + wc * p2;
            float v = sMk[j + 1] ? (s2 * c + t2) : 0.f;
            sBh[j * (2 * SBW) + hoff] = __float2half_rn(v);  // safe: sliding window
            p0 = p1; p1 = p2;
        }
    }
    __syncthreads();

    // ================ GEMM3: O = W3 @ Y2, two N-halves, direct global ================
    {
        float* ob = out + (size_t)bb * CTOT * LLEN;
        #pragma unroll
        for (int h = 0; h < 2; h++) {
            #pragma unroll
            for (int mt = 0; mt < 2; mt++)
                #pragma unroll
                for (int nt = 0; nt < 4; nt++)
                    #pragma unroll
                    for (int q = 0; q < 4; q++) acc[mt][nt][q] = 0.f;
            {
                const unsigned* wp = g_w3f + abase;
                #pragma unroll
                for (int it = 0; it < 16; it++) {
                    uint4 q1 = *(const uint4*)(wp + it * 256);
                    uint4 q2 = *(const uint4*)(wp + it * 256 + 4);
                    unsigned a0[4] = { q1.x, q1.z, q1.y, q1.w };
                    unsigned a1[4] = { q2.x, q2.z, q2.y, q2.w };
                    const int kw = it * 8 + 2 * tg;
                    #pragma unroll
                    for (int nt = 0; nt < 4; nt++) {
                        uint2 Bv = *(const uint2*)&sB[((h * 4 + nt) * 8 + g) * SBW + kw];
                        mma16(acc[0][nt], a0, Bv.x, Bv.y);
                        mma16(acc[1][nt], a1, Bv.x, Bv.y);
                    }
                }
            }
            // epilogue: mish + bn3 + mask -> even output channels, STG.64 pairs
            {
                float sv[4], tv[4];
                #pragma unroll
                for (int q = 0; q < 4; q++) { sv[q] = sS3[rows4[q]]; tv[q] = sT3[rows4[q]]; }
                #pragma unroll
                for (int mt = 0; mt < 2; mt++)
                    #pragma unroll
                    for (int nt = 0; nt < 4; nt++)
                        #pragma unroll
                        for (int qp = 0; qp < 2; qp++) {
                            int ri = mt * 2 + qp;
                            int c0 = (h * 4 + nt) * 8 + 2 * tg;
                            int l = l0 + c0;
                            if (c0 < TN - 1 && l + 1 < LLEN) {
                                float y0 = mishf(acc[mt][nt][2 * qp + 0]);
                                float y1 = mishf(acc[mt][nt][2 * qp + 1]);
                                float z0 = sv[ri] * y0 + tv[ri];
                                float z1 = sv[ri] * y1 + tv[ri];
                                float2 zz;
                                zz.x = sMk[c0 + 1] ? z0 : 0.f;
                                zz.y = sMk[c0 + 2] ? z1 : 0.f;
                                *(float2*)&ob[(size_t)(2 * rows4[ri]) * LLEN + l] = zz;
                            }
                        }
            }
        }
    }
}

// ---------------- launch ----------------
extern "C" void kernel_launch(void* const* d_in, const int* in_sizes, int n_in,
                              void* d_out, int out_size) {
    (void)in_sizes; (void)n_in; (void)out_size;
    const float* x   = (const float*)d_in[0];
    const void*  mk  = d_in[1];
    const float* w1  = (const float*)d_in[2];
    const float* w2  = (const float*)d_in[3];
    const float* w3  = (const float*)d_in[4];
    const float* b1w = (const float*)d_in[5];
    const float* b1b = (const float*)d_in[6];
    const float* b1m = (const float*)d_in[7];
    const float* b1v = (const float*)d_in[8];
    const float* b2w = (const float*)d_in[9];
    const float* b2b = (const float*)d_in[10];
    const float* b2m = (const float*)d_in[11];
    const float* b2v = (const float*)d_in[12];
    const float* b3w = (const float*)d_in[13];
    const float* b3b = (const float*)d_in[14];
    const float* b3m = (const float*)d_in[15];
    const float* b3v = (const float*)d_in[16];
    float* out = (float*)d_out;

    const int smem_bytes = NCOL * SBW * (int)sizeof(unsigned);
    cudaFuncSetAttribute(fused_kernel, cudaFuncAttributeMaxDynamicSharedMemorySize, smem_bytes);

    detect_kernel<<<DET_BLOCKS, 256>>>((const unsigned char*)mk, w1, w3);

    dim3 grid(LTILES, BATCH);
    fused_kernel<<<grid, NTHREADS, smem_bytes>>>(
        x, mk,
        b1w, b1b, b1m, b1v,
        b2w, b2b, b2m, b2v,
        b3w, b3b, b3m, b3v,
        w2, out);
}